// round 5
// baseline (speedup 1.0000x reference)
#include <cuda_runtime.h>
#include <cstdint>
#include <math.h>

#define BATCH 2
#define SEQ   2048
#define DMODEL 1024
#define NHEAD 16
#define HDIM  64
#define MTOT  (BATCH * SEQ)   // 4096

// Scratch (allocation-free rule: __device__ globals)
__device__ float g_q[(size_t)MTOT * DMODEL];        // 16 MB
__device__ float g_kv[(size_t)MTOT * 2 * DMODEL];   // 32 MB
__device__ float g_y[(size_t)MTOT * DMODEL];        // 16 MB

// ---------------------------------------------------------------------------
// mma.sync tf32: D(16x8) += A(16x8 row) * B(8x8 col), fp32 accum
// ---------------------------------------------------------------------------
__device__ __forceinline__ void mma_tf32(float* c, const uint32_t* a,
                                         const uint32_t* b) {
    asm volatile(
        "mma.sync.aligned.m16n8k8.row.col.f32.tf32.tf32.f32 "
        "{%0,%1,%2,%3}, {%4,%5,%6,%7}, {%8,%9}, {%0,%1,%2,%3};"
        : "+f"(c[0]), "+f"(c[1]), "+f"(c[2]), "+f"(c[3])
        : "r"(a[0]), "r"(a[1]), "r"(a[2]), "r"(a[3]),
          "r"(b[0]), "r"(b[1]));
}

__device__ __forceinline__ uint32_t f2tf32(float f) {
    uint32_t r;
    asm("cvt.rna.tf32.f32 %0, %1;" : "=r"(r) : "f"(f));
    return r;
}

// ---------------------------------------------------------------------------
// tf32 tensor-core GEMM: C[M,N] = A[M,K] @ W[N,K]^T + bias[N]  (unchanged R3)
// ---------------------------------------------------------------------------
#define GSTRIDE 36
#define GBUF (128 * GSTRIDE)

__global__ __launch_bounds__(256) void mma_gemm_nt_bias(
    const float* __restrict__ A, const float* __restrict__ W,
    const float* __restrict__ bias, float* __restrict__ C,
    int N, int K)
{
    extern __shared__ uint32_t sh[];
    const int tid = threadIdx.x;
    const int wid = tid >> 5;
    const int lane = tid & 31;
    const int grp = lane >> 2;
    const int qid = lane & 3;

    const int bm = blockIdx.y * 128;
    const int bn = blockIdx.x * 128;
    const int rbase = (wid & 3) * 32;
    const int nbase = (wid >> 2) * 64;

    const int lrow = tid >> 1;
    const int kbase = (tid & 1) * 16;
    const float* Ap = A + (size_t)(bm + lrow) * K + kbase;
    const float* Wp = W + (size_t)(bn + lrow) * K + kbase;
    const int soff = lrow * GSTRIDE + kbase;

    float acc[2][8][4];
#pragma unroll
    for (int mi = 0; mi < 2; mi++)
#pragma unroll
        for (int ni = 0; ni < 8; ni++)
#pragma unroll
            for (int v = 0; v < 4; v++) acc[mi][ni][v] = 0.0f;

    const int NC = K / 32;

#pragma unroll
    for (int u = 0; u < 4; u++) {
        float4 t = *(const float4*)(Ap + 4 * u);
        float4 t2;
        t2.x = __uint_as_float(f2tf32(t.x));
        t2.y = __uint_as_float(f2tf32(t.y));
        t2.z = __uint_as_float(f2tf32(t.z));
        t2.w = __uint_as_float(f2tf32(t.w));
        *(float4*)&sh[soff + 4 * u] = t2;
    }
#pragma unroll
    for (int u = 0; u < 4; u++) {
        float4 t = *(const float4*)(Wp + 4 * u);
        float4 t2;
        t2.x = __uint_as_float(f2tf32(t.x));
        t2.y = __uint_as_float(f2tf32(t.y));
        t2.z = __uint_as_float(f2tf32(t.z));
        t2.w = __uint_as_float(f2tf32(t.w));
        *(float4*)&sh[GBUF + soff + 4 * u] = t2;
    }
    __syncthreads();

    float4 pf[8];

    for (int c = 0; c < NC; c++) {
        const uint32_t* Ab = sh + (c & 1) * (2 * GBUF);
        const uint32_t* Wb = Ab + GBUF;

        if (c + 1 < NC) {
            const int k0 = (c + 1) * 32;
#pragma unroll
            for (int u = 0; u < 4; u++) pf[u] = *(const float4*)(Ap + k0 + 4 * u);
#pragma unroll
            for (int u = 0; u < 4; u++) pf[4 + u] = *(const float4*)(Wp + k0 + 4 * u);
        }

#pragma unroll
        for (int ks = 0; ks < 4; ks++) {
            uint32_t afr[2][4];
#pragma unroll
            for (int mi = 0; mi < 2; mi++) {
                const int r0 = rbase + mi * 16 + grp;
                const int col = ks * 8 + qid;
                afr[mi][0] = Ab[r0 * GSTRIDE + col];
                afr[mi][1] = Ab[(r0 + 8) * GSTRIDE + col];
                afr[mi][2] = Ab[r0 * GSTRIDE + col + 4];
                afr[mi][3] = Ab[(r0 + 8) * GSTRIDE + col + 4];
            }
            uint32_t bfr[8][2];
#pragma unroll
            for (int ni = 0; ni < 8; ni++) {
                const int nrow = nbase + ni * 8 + grp;
                bfr[ni][0] = Wb[nrow * GSTRIDE + ks * 8 + qid];
                bfr[ni][1] = Wb[nrow * GSTRIDE + ks * 8 + qid + 4];
            }
#pragma unroll
            for (int mi = 0; mi < 2; mi++)
#pragma unroll
                for (int ni = 0; ni < 8; ni++)
                    mma_tf32(acc[mi][ni], afr[mi], bfr[ni]);
        }

        if (c + 1 < NC) {
            uint32_t* Ab2 = sh + ((c + 1) & 1) * (2 * GBUF);
            uint32_t* Wb2 = Ab2 + GBUF;
#pragma unroll
            for (int u = 0; u < 4; u++) {
                float4 t = pf[u];
                float4 t2;
                t2.x = __uint_as_float(f2tf32(t.x));
                t2.y = __uint_as_float(f2tf32(t.y));
                t2.z = __uint_as_float(f2tf32(t.z));
                t2.w = __uint_as_float(f2tf32(t.w));
                *(float4*)&Ab2[soff + 4 * u] = t2;
            }
#pragma unroll
            for (int u = 0; u < 4; u++) {
                float4 t = pf[4 + u];
                float4 t2;
                t2.x = __uint_as_float(f2tf32(t.x));
                t2.y = __uint_as_float(f2tf32(t.y));
                t2.z = __uint_as_float(f2tf32(t.z));
                t2.w = __uint_as_float(f2tf32(t.w));
                *(float4*)&Wb2[soff + 4 * u] = t2;
            }
        }
        __syncthreads();
    }

#pragma unroll
    for (int mi = 0; mi < 2; mi++) {
        const int row = bm + rbase + mi * 16 + grp;
#pragma unroll
        for (int ni = 0; ni < 8; ni++) {
            const int col = bn + nbase + ni * 8 + 2 * qid;
            const float2 bv = *(const float2*)(bias + col);
            float2 o0, o1;
            o0.x = acc[mi][ni][0] + bv.x;
            o0.y = acc[mi][ni][1] + bv.y;
            o1.x = acc[mi][ni][2] + bv.x;
            o1.y = acc[mi][ni][3] + bv.y;
            *(float2*)(C + (size_t)row * N + col) = o0;
            *(float2*)(C + (size_t)(row + 8) * N + col) = o1;
        }
    }
}

// ---------------------------------------------------------------------------
// Tensor-core flash attention (tf32 MMA, fp32 softmax), ALiBi + causal.
// CTA: 128 queries x 1 head. 8 warps x 16 query rows. Key tiles of 64.
// ---------------------------------------------------------------------------
#define STR 68   // smem row stride (floats); 68 mod 32 = 4 -> conflict-free frags

__global__ __launch_bounds__(256) void attn_mma(
    const float* __restrict__ q, const float* __restrict__ kv,
    float* __restrict__ y)
{
    extern __shared__ float smf[];
    uint32_t* sQu = (uint32_t*)smf;                 // 128*STR : Q tile, then P
    uint32_t* sKu = sQu + 128 * STR;                // 64*STR  : K [key][d]
    uint32_t* sVu = sKu + 64 * STR;                 // 64*STR  : V [d][key]

    const int tid = threadIdx.x;
    const int wid = tid >> 5, lane = tid & 31;
    const int grp = lane >> 2, qid = lane & 3;
    const int qt = (int)gridDim.x - 1 - (int)blockIdx.x;   // big tiles first
    const int h = blockIdx.y, b = blockIdx.z;
    const int q0 = qt * 128;
    const float slope = (float)(h + 1) * (1.0f / NHEAD);

    // ---- Q load (warp-local rows: tid>>1 gives warp w rows 16w..16w+15) ----
    {
        const int row = tid >> 1;
        const int ch = (tid & 1) * 32;
        const float* src = q + ((size_t)(b * SEQ + q0 + row)) * DMODEL + h * HDIM + ch;
        uint32_t* dst = sQu + row * STR + ch;
#pragma unroll
        for (int u = 0; u < 8; u++) {
            float4 v = *(const float4*)(src + 4 * u);
            dst[4 * u + 0] = f2tf32(v.x); dst[4 * u + 1] = f2tf32(v.y);
            dst[4 * u + 2] = f2tf32(v.z); dst[4 * u + 3] = f2tf32(v.w);
        }
    }
    __syncwarp();

    const int prow = (16 * wid + grp) * STR;
    uint32_t qfr[8][4];
#pragma unroll
    for (int ks = 0; ks < 8; ks++) {
        const int c0 = ks * 8 + qid;
        qfr[ks][0] = sQu[prow + c0];
        qfr[ks][1] = sQu[prow + 8 * STR + c0];
        qfr[ks][2] = sQu[prow + c0 + 4];
        qfr[ks][3] = sQu[prow + 8 * STR + c0 + 4];
    }
    __syncwarp();

    float m_[2] = {-1e30f, -1e30f};
    float l_[2] = {0.0f, 0.0f};
    float oacc[8][4];
#pragma unroll
    for (int ni = 0; ni < 8; ni++)
#pragma unroll
        for (int v = 0; v < 4; v++) oacc[ni][v] = 0.0f;

    const int qg0 = q0 + 16 * wid + grp;   // row for c0/c1; c2/c3 at qg0+8
    const int ktmax = 2 * qt + 1;

    for (int kt = 0; kt <= ktmax; kt++) {
        const int k0 = kt * 64;
        __syncthreads();   // prior tile's frag reads of sK/sV complete

        // ---- load K [key][d] and V [d][key] (tf32-converted) ----
        {
            const int key = tid >> 2, db = (tid & 3) * 16;
            const float* src = kv + ((size_t)(b * SEQ + k0 + key)) * (2 * DMODEL) + h * HDIM + db;
            uint32_t* dst = sKu + key * STR + db;
#pragma unroll
            for (int u = 0; u < 4; u++) {
                float4 v = *(const float4*)(src + 4 * u);
                dst[4 * u + 0] = f2tf32(v.x); dst[4 * u + 1] = f2tf32(v.y);
                dst[4 * u + 2] = f2tf32(v.z); dst[4 * u + 3] = f2tf32(v.w);
            }
            const int vkey = tid & 63, vdb = (tid >> 6) * 16;
            const float* vsrc = kv + ((size_t)(b * SEQ + k0 + vkey)) * (2 * DMODEL)
                                + DMODEL + h * HDIM + vdb;
#pragma unroll
            for (int u = 0; u < 4; u++) {
                float4 v = *(const float4*)(vsrc + 4 * u);
                sVu[(vdb + 4 * u + 0) * STR + vkey] = f2tf32(v.x);
                sVu[(vdb + 4 * u + 1) * STR + vkey] = f2tf32(v.y);
                sVu[(vdb + 4 * u + 2) * STR + vkey] = f2tf32(v.z);
                sVu[(vdb + 4 * u + 3) * STR + vkey] = f2tf32(v.w);
            }
        }
        __syncthreads();

        // ---- S = Q @ K^T ----
        float sacc[8][4];
#pragma unroll
        for (int ni = 0; ni < 8; ni++)
#pragma unroll
            for (int v = 0; v < 4; v++) sacc[ni][v] = 0.0f;

#pragma unroll
        for (int ks = 0; ks < 8; ks++) {
#pragma unroll
            for (int ni = 0; ni < 8; ni++) {
                uint32_t bfr[2];
                const int ba = (ni * 8 + grp) * STR + ks * 8 + qid;
                bfr[0] = sKu[ba];
                bfr[1] = sKu[ba + 4];
                mma_tf32(sacc[ni], qfr[ks], bfr);
            }
        }

        // ---- scale + ALiBi + causal mask (fp32) ----
        const bool needmask = (kt >= 2 * qt);
        float mx0 = -1e30f, mx1 = -1e30f;
#pragma unroll
        for (int ni = 0; ni < 8; ni++) {
            const int key0 = k0 + ni * 8 + 2 * qid;
            const float d0 = (float)(key0 - qg0);
            float v0 = fmaf(sacc[ni][0], 0.125f, slope * d0);
            float v1 = fmaf(sacc[ni][1], 0.125f, slope * (d0 + 1.0f));
            float v2 = fmaf(sacc[ni][2], 0.125f, slope * (d0 - 8.0f));
            float v3 = fmaf(sacc[ni][3], 0.125f, slope * (d0 - 7.0f));
            if (needmask) {
                if (key0     > qg0)     v0 = -1e30f;
                if (key0 + 1 > qg0)     v1 = -1e30f;
                if (key0     > qg0 + 8) v2 = -1e30f;
                if (key0 + 1 > qg0 + 8) v3 = -1e30f;
            }
            sacc[ni][0] = v0; sacc[ni][1] = v1;
            sacc[ni][2] = v2; sacc[ni][3] = v3;
            mx0 = fmaxf(mx0, fmaxf(v0, v1));
            mx1 = fmaxf(mx1, fmaxf(v2, v3));
        }
        mx0 = fmaxf(mx0, __shfl_xor_sync(0xffffffffu, mx0, 1));
        mx0 = fmaxf(mx0, __shfl_xor_sync(0xffffffffu, mx0, 2));
        mx1 = fmaxf(mx1, __shfl_xor_sync(0xffffffffu, mx1, 1));
        mx1 = fmaxf(mx1, __shfl_xor_sync(0xffffffffu, mx1, 2));

        const float mn0 = fmaxf(m_[0], mx0);
        const float mn1 = fmaxf(m_[1], mx1);
        const float sc0 = __expf(m_[0] - mn0);
        const float sc1 = __expf(m_[1] - mn1);
        m_[0] = mn0; m_[1] = mn1;

        float rs0 = 0.0f, rs1 = 0.0f;
#pragma unroll
        for (int ni = 0; ni < 8; ni++) {
            const float p0 = __expf(sacc[ni][0] - mn0);
            const float p1 = __expf(sacc[ni][1] - mn0);
            const float p2 = __expf(sacc[ni][2] - mn1);
            const float p3 = __expf(sacc[ni][3] - mn1);
            rs0 += p0 + p1;
            rs1 += p2 + p3;
            uint2 w0; w0.x = f2tf32(p0); w0.y = f2tf32(p1);
            *(uint2*)&sQu[prow + ni * 8 + 2 * qid] = w0;
            uint2 w1; w1.x = f2tf32(p2); w1.y = f2tf32(p3);
            *(uint2*)&sQu[prow + 8 * STR + ni * 8 + 2 * qid] = w1;
        }
        rs0 += __shfl_xor_sync(0xffffffffu, rs0, 1);
        rs0 += __shfl_xor_sync(0xffffffffu, rs0, 2);
        rs1 += __shfl_xor_sync(0xffffffffu, rs1, 1);
        rs1 += __shfl_xor_sync(0xffffffffu, rs1, 2);
        l_[0] = l_[0] * sc0 + rs0;
        l_[1] = l_[1] * sc1 + rs1;

#pragma unroll
        for (int ni = 0; ni < 8; ni++) {
            oacc[ni][0] *= sc0; oacc[ni][1] *= sc0;
            oacc[ni][2] *= sc1; oacc[ni][3] *= sc1;
        }
        __syncwarp();   // P visible to own warp

        // ---- O += P @ V ----
#pragma unroll
        for (int ks = 0; ks < 8; ks++) {
            uint32_t pa[4];
            const int c0 = ks * 8 + qid;
            pa[0] = sQu[prow + c0];
            pa[1] = sQu[prow + 8 * STR + c0];
            pa[2] = sQu[prow + c0 + 4];
            pa[3] = sQu[prow + 8 * STR + c0 + 4];
#pragma unroll
            for (int ni = 0; ni < 8; ni++) {
                uint32_t bfr[2];
                const int ba = (ni * 8 + grp) * STR + ks * 8 + qid;
                bfr[0] = sVu[ba];
                bfr[1] = sVu[ba + 4];
                mma_tf32(oacc[ni], pa, bfr);
            }
        }
    }

    // ---- epilogue ----
    const float inv0 = 1.0f / l_[0];
    const float inv1 = 1.0f / l_[1];
    float* d0p = y + ((size_t)(b * SEQ + qg0)) * DMODEL + h * HDIM;
    float* d1p = d0p + (size_t)8 * DMODEL;
#pragma unroll
    for (int ni = 0; ni < 8; ni++) {
        const int c = ni * 8 + 2 * qid;
        float2 o0; o0.x = oacc[ni][0] * inv0; o0.y = oacc[ni][1] * inv0;
        *(float2*)(d0p + c) = o0;
        float2 o1; o1.x = oacc[ni][2] * inv1; o1.y = oacc[ni][3] * inv1;
        *(float2*)(d1p + c) = o1;
    }
}

// ---------------------------------------------------------------------------
extern "C" void kernel_launch(void* const* d_in, const int* in_sizes, int n_in,
                              void* d_out, int out_size)
{
    const float* x   = (const float*)d_in[0];
    const float* Wq  = (const float*)d_in[2];
    const float* bq  = (const float*)d_in[3];
    const float* Wkv = (const float*)d_in[4];
    const float* bkv = (const float*)d_in[5];
    const float* Wo  = (const float*)d_in[6];
    const float* bo  = (const float*)d_in[7];
    float* out = (float*)d_out;

    void *pq, *pkv, *py;
    cudaGetSymbolAddress(&pq, g_q);
    cudaGetSymbolAddress(&pkv, g_kv);
    cudaGetSymbolAddress(&py, g_y);
    float* qb  = (float*)pq;
    float* kvb = (float*)pkv;
    float* yb  = (float*)py;

    const int gemm_smem = 2 * 2 * GBUF * 4;   // 73728 B
    cudaFuncSetAttribute(mma_gemm_nt_bias,
                         cudaFuncAttributeMaxDynamicSharedMemorySize, gemm_smem);

    mma_gemm_nt_bias<<<dim3(DMODEL / 128, MTOT / 128), 256, gemm_smem>>>(
        x, Wq, bq, qb, DMODEL, DMODEL);

    mma_gemm_nt_bias<<<dim3(2 * DMODEL / 128, MTOT / 128), 256, gemm_smem>>>(
        x, Wkv, bkv, kvb, 2 * DMODEL, DMODEL);

    const int attn_smem = (128 + 64 + 64) * STR * 4;   // 69632 B
    cudaFuncSetAttribute(attn_mma,
                         cudaFuncAttributeMaxDynamicSharedMemorySize, attn_smem);
    attn_mma<<<dim3(SEQ / 128, NHEAD, BATCH), 256, attn_smem>>>(qb, kvb, yb);

    mma_gemm_nt_bias<<<dim3(DMODEL / 128, MTOT / 128), 256, gemm_smem>>>(
        yb, Wo, bo, out, DMODEL, DMODEL);
}

// round 6
// speedup vs baseline: 2.0241x; 2.0241x over previous
#include <cuda_runtime.h>
#include <cuda_fp16.h>
#include <cstdint>
#include <math.h>

#define BATCH 2
#define SEQ   2048
#define DMODEL 1024
#define NHEAD 16
#define HDIM  64
#define MTOT  (BATCH * SEQ)   // 4096

// fp16 scratch (allocation-free rule: __device__ globals)
__device__ __half g_q[(size_t)MTOT * DMODEL];        // 8 MB
__device__ __half g_kv[(size_t)MTOT * 2 * DMODEL];   // 16 MB
__device__ __half g_y[(size_t)MTOT * DMODEL];        // 8 MB

// ---------------------------------------------------------------------------
// helpers
// ---------------------------------------------------------------------------
__device__ __forceinline__ uint32_t smem_u32(const void* p) {
    uint32_t a;
    asm("{ .reg .u64 t; cvta.to.shared.u64 t, %1; cvt.u32.u64 %0, t; }"
        : "=r"(a) : "l"(p));
    return a;
}

__device__ __forceinline__ uint32_t pkf16(float lo, float hi) {
    uint32_t r;
    asm("cvt.rn.f16x2.f32 %0, %1, %2;" : "=r"(r) : "f"(hi), "f"(lo));
    return r;
}

// D(16x8,f32) += A(16x16 row,f16) * B(16x8 col,f16)
__device__ __forceinline__ void mma_f16(float* c, const uint32_t* a,
                                        uint32_t b0, uint32_t b1) {
    asm volatile(
        "mma.sync.aligned.m16n8k16.row.col.f32.f16.f16.f32 "
        "{%0,%1,%2,%3}, {%4,%5,%6,%7}, {%8,%9}, {%0,%1,%2,%3};"
        : "+f"(c[0]), "+f"(c[1]), "+f"(c[2]), "+f"(c[3])
        : "r"(a[0]), "r"(a[1]), "r"(a[2]), "r"(a[3]), "r"(b0), "r"(b1));
}

__device__ __forceinline__ void ldsm4(uint32_t* r, uint32_t addr) {
    asm volatile("ldmatrix.sync.aligned.m8n8.x4.shared.b16 {%0,%1,%2,%3}, [%4];"
                 : "=r"(r[0]), "=r"(r[1]), "=r"(r[2]), "=r"(r[3]) : "r"(addr));
}

__device__ __forceinline__ void ldsm4t(uint32_t* r, uint32_t addr) {
    asm volatile("ldmatrix.sync.aligned.m8n8.x4.trans.shared.b16 {%0,%1,%2,%3}, [%4];"
                 : "=r"(r[0]), "=r"(r[1]), "=r"(r[2]), "=r"(r[3]) : "r"(addr));
}

__device__ __forceinline__ void sts128(uint32_t addr, const uint32_t* v) {
    asm volatile("st.shared.v4.b32 [%0], {%1,%2,%3,%4};"
                 :: "r"(addr), "r"(v[0]), "r"(v[1]), "r"(v[2]), "r"(v[3]) : "memory");
}

__device__ __forceinline__ void cp16(uint32_t dst, const void* src) {
    asm volatile("cp.async.cg.shared.global [%0], [%1], 16;"
                 :: "r"(dst), "l"(src) : "memory");
}
#define CP_COMMIT() asm volatile("cp.async.commit_group;" ::: "memory")
#define CP_WAIT0()  asm volatile("cp.async.wait_group 0;" ::: "memory")
#define CP_WAIT1()  asm volatile("cp.async.wait_group 1;" ::: "memory")

// 16 k-elements -> 8 packed f16x2 regs
__device__ __forceinline__ void load16(const float* p, uint32_t* r) {
#pragma unroll
    for (int u = 0; u < 4; u++) {
        float4 v = *(const float4*)(p + 4 * u);
        r[2 * u]     = pkf16(v.x, v.y);
        r[2 * u + 1] = pkf16(v.z, v.w);
    }
}
__device__ __forceinline__ void load16(const __half* p, uint32_t* r) {
    uint4 a = *(const uint4*)(p);
    uint4 b = *(const uint4*)(p + 8);
    r[0] = a.x; r[1] = a.y; r[2] = a.z; r[3] = a.w;
    r[4] = b.x; r[5] = b.y; r[6] = b.z; r[7] = b.w;
}

__device__ __forceinline__ void st_pair(__half* C, size_t off, float v0, float v1) {
    *(uint32_t*)(C + off) = pkf16(v0, v1);
}
__device__ __forceinline__ void st_pair(float* C, size_t off, float v0, float v1) {
    float2 t; t.x = v0; t.y = v1;
    *(float2*)(C + off) = t;
}

// ---------------------------------------------------------------------------
// fp16 tensor-core GEMM: C[M,N] = A[M,K] @ W[N,K]^T + bias[N]
// CTA 128x128, BK=32, 8 warps (4m x 2n), warp tile 32x64, double-buffered.
// smem stride 40 halfs (80B): ldmatrix rows hit 8 distinct bank groups.
// ---------------------------------------------------------------------------
#define GAS 40                 // smem row stride in halfs
#define GBUFB 20480            // bytes per buffer (A 10240 + W 10240)

template<typename AT, typename OT>
__device__ __forceinline__ void gemm_body(
    const AT* __restrict__ A, const float* __restrict__ W,
    const float* __restrict__ bias, OT* __restrict__ C,
    int N, int K, int bm, int bn, uint32_t sb)
{
    const int tid = threadIdx.x, wid = tid >> 5, lane = tid & 31;
    const int grp = lane >> 2, qid = lane & 3;
    const int rbase = (wid & 3) * 32;
    const int nbase = (wid >> 2) * 64;

    const int lrow = tid >> 1, kb16 = (tid & 1) * 16;
    const AT* Ap = A + (size_t)(bm + lrow) * K + kb16;
    const float* Wp = W + (size_t)(bn + lrow) * K + kb16;
    const uint32_t sts_off = (uint32_t)(lrow * GAS + kb16) * 2u;

    float acc[2][8][4];
#pragma unroll
    for (int mi = 0; mi < 2; mi++)
#pragma unroll
        for (int ni = 0; ni < 8; ni++)
#pragma unroll
            for (int v = 0; v < 4; v++) acc[mi][ni][v] = 0.0f;

    const int NC = K / 32;
    uint32_t pa[8], pw[8];

    load16(Ap, pa);
    load16(Wp, pw);
    sts128(sb + sts_off, pa);
    sts128(sb + sts_off + 16, pa + 4);
    sts128(sb + 10240u + sts_off, pw);
    sts128(sb + 10240u + sts_off + 16, pw + 4);
    __syncthreads();

    // A-frag base: lanes 0-15 -> rows 0-15 k0 ; lanes 16-31 -> rows 0-15 k+8
    const uint32_t a_lo = (uint32_t)((lane & 15) * GAS + (lane >> 4) * 8) * 2u;
    // B-frag base: [n0-7,k0][n0-7,k8][n8-15,k0][n8-15,k8]
    const uint32_t b_lo = (uint32_t)((((lane >> 4) & 1) * 8 + (lane & 7)) * GAS
                                     + ((lane >> 3) & 1) * 8) * 2u;

    for (int c = 0; c < NC; c++) {
        const uint32_t Ab = sb + (uint32_t)(c & 1) * GBUFB;
        const uint32_t Bb = Ab + 10240u;

        if (c + 1 < NC) {
            load16(Ap + (c + 1) * 32, pa);
            load16(Wp + (c + 1) * 32, pw);
        }

#pragma unroll
        for (int ks = 0; ks < 2; ks++) {
            uint32_t af[2][4];
#pragma unroll
            for (int mi = 0; mi < 2; mi++)
                ldsm4(af[mi], Ab + a_lo +
                      (uint32_t)(((rbase + mi * 16) * GAS + ks * 16) * 2));
            uint32_t bf[16];
#pragma unroll
            for (int p = 0; p < 4; p++)
                ldsm4(bf + 4 * p, Bb + b_lo +
                      (uint32_t)(((nbase + p * 16) * GAS + ks * 16) * 2));
#pragma unroll
            for (int mi = 0; mi < 2; mi++)
#pragma unroll
                for (int ni = 0; ni < 8; ni++)
                    mma_f16(acc[mi][ni], af[mi], bf[2 * ni], bf[2 * ni + 1]);
        }

        if (c + 1 < NC) {
            const uint32_t Ab2 = sb + (uint32_t)((c + 1) & 1) * GBUFB;
            sts128(Ab2 + sts_off, pa);
            sts128(Ab2 + sts_off + 16, pa + 4);
            sts128(Ab2 + 10240u + sts_off, pw);
            sts128(Ab2 + 10240u + sts_off + 16, pw + 4);
        }
        __syncthreads();
    }

#pragma unroll
    for (int mi = 0; mi < 2; mi++) {
        const int row = bm + rbase + mi * 16 + grp;
#pragma unroll
        for (int ni = 0; ni < 8; ni++) {
            const int col = bn + nbase + ni * 8 + 2 * qid;
            const float2 bv = *(const float2*)(bias + col);
            st_pair(C, (size_t)row * N + col,
                    acc[mi][ni][0] + bv.x, acc[mi][ni][1] + bv.y);
            st_pair(C, (size_t)(row + 8) * N + col,
                    acc[mi][ni][2] + bv.x, acc[mi][ni][3] + bv.y);
        }
    }
}

__global__ __launch_bounds__(256, 2) void gemm_f2h(
    const float* __restrict__ A, const float* __restrict__ W,
    const float* __restrict__ bias, __half* __restrict__ C, int N, int K)
{
    extern __shared__ __half smh[];
    gemm_body<float, __half>(A, W, bias, C, N, K,
                             blockIdx.y * 128, blockIdx.x * 128, smem_u32(smh));
}

__global__ __launch_bounds__(256, 2) void gemm_h2f(
    const __half* __restrict__ A, const float* __restrict__ W,
    const float* __restrict__ bias, float* __restrict__ C, int N, int K)
{
    extern __shared__ __half smh[];
    gemm_body<__half, float>(A, W, bias, C, N, K,
                             blockIdx.y * 128, blockIdx.x * 128, smem_u32(smh));
}

// ---------------------------------------------------------------------------
// fp16 tensor-core flash attention, ALiBi + causal, fp32 softmax.
// CTA: 128 queries x head; 8 warps x 16 rows; 64-key tiles; cp.async 2-stage.
// P stays in registers (C-frag -> A-frag identity). V via ldmatrix.trans.
// ---------------------------------------------------------------------------
#define KSTR 72                 // smem row stride in halfs (144B)
#define KTILE_B (64 * KSTR * 2) // 9216 B per K or V tile
#define ABUF_B (2 * KTILE_B)    // 18432 B per stage (K+V)

__global__ __launch_bounds__(256) void attn_mma(
    const __half* __restrict__ q, const __half* __restrict__ kv,
    __half* __restrict__ y)
{
    extern __shared__ __half smh[];
    const uint32_t sb = smem_u32(smh);

    const int tid = threadIdx.x;
    const int wid = tid >> 5, lane = tid & 31;
    const int grp = lane >> 2, qid = lane & 3;
    const int qt = (int)gridDim.x - 1 - (int)blockIdx.x;   // big tiles first
    const int h = blockIdx.y, b = blockIdx.z;
    const int q0 = qt * 128;
    const float slope = (float)(h + 1) * (1.0f / NHEAD);

    // ---- stage Q tile (aliases stage-0 buffers), extract frags ----
    {
        const int row = tid >> 1;
        const int seg = (tid & 1) * 4;
        const __half* src = q + ((size_t)(b * SEQ + q0 + row)) * DMODEL
                            + h * HDIM + seg * 8;
        const uint32_t dst = sb + (uint32_t)(row * KSTR * 2 + seg * 16);
#pragma unroll
        for (int u = 0; u < 4; u++) cp16(dst + u * 16, src + u * 8);
    }
    CP_COMMIT();
    CP_WAIT0();
    __syncthreads();

    const uint32_t a_lo = (uint32_t)((lane & 15) * KSTR + (lane >> 4) * 8) * 2u;
    uint32_t qfr[4][4];
    {
        const uint32_t qwarp = sb + (uint32_t)(16 * wid * KSTR * 2) + a_lo;
#pragma unroll
        for (int ks = 0; ks < 4; ks++) ldsm4(qfr[ks], qwarp + ks * 32);
    }
    __syncthreads();   // done reading Q staging; buffers reusable

    // B-frag (K) lane offset: [n0-7,k0][n0-7,k8][n8-15,k0][n8-15,k8]
    const uint32_t b_lo = (uint32_t)((((lane >> 4) & 1) * 8 + (lane & 7)) * KSTR
                                     + ((lane >> 3) & 1) * 8) * 2u;
    // V trans-frag lane offset: [key0-7,d0][key8-15,d0][key0-7,d8][key8-15,d8]
    const uint32_t v_lo = (uint32_t)(((lane & 7) + ((lane >> 3) & 1) * 8) * KSTR
                                     + (lane >> 4) * 8) * 2u;

    float m_[2] = {-1e30f, -1e30f};
    float l_[2] = {0.0f, 0.0f};
    float oacc[8][4];
#pragma unroll
    for (int ni = 0; ni < 8; ni++)
#pragma unroll
        for (int v = 0; v < 4; v++) oacc[ni][v] = 0.0f;

    const int qg0 = q0 + 16 * wid + grp;
    const int ktmax = 2 * qt + 1;

    // cp.async loader lambda-equivalent
    const int krow = tid >> 2, kseg = tid & 3;
    const __half* kvbase = kv + ((size_t)(b * SEQ + krow)) * (2 * DMODEL) + h * HDIM;

    // prologue: issue tile 0 into stage 0
    {
        const __half* src = kvbase;   // k0 = 0
        const uint32_t dK = sb + (uint32_t)(krow * KSTR * 2);
        const uint32_t dV = dK + (uint32_t)KTILE_B;
        cp16(dK + kseg * 16, src + kseg * 8);
        cp16(dK + (kseg + 4) * 16, src + (kseg + 4) * 8);
        cp16(dV + kseg * 16, src + DMODEL + kseg * 8);
        cp16(dV + (kseg + 4) * 16, src + DMODEL + (kseg + 4) * 8);
    }
    CP_COMMIT();

    for (int kt = 0; kt <= ktmax; kt++) {
        const int k0 = kt * 64;
        const uint32_t bK = sb + (uint32_t)(kt & 1) * ABUF_B;
        const uint32_t bV = bK + (uint32_t)KTILE_B;

        if (kt < ktmax) {
            const __half* src = kvbase + (size_t)(k0 + 64) * (2 * DMODEL);
            const uint32_t dK = sb + (uint32_t)((kt + 1) & 1) * ABUF_B
                                + (uint32_t)(krow * KSTR * 2);
            const uint32_t dV = dK + (uint32_t)KTILE_B;
            cp16(dK + kseg * 16, src + kseg * 8);
            cp16(dK + (kseg + 4) * 16, src + (kseg + 4) * 8);
            cp16(dV + kseg * 16, src + DMODEL + kseg * 8);
            cp16(dV + (kseg + 4) * 16, src + DMODEL + (kseg + 4) * 8);
            CP_COMMIT();
            CP_WAIT1();
        } else {
            CP_WAIT0();
        }
        __syncthreads();

        // ---- S = Q @ K^T ----
        float sacc[8][4];
#pragma unroll
        for (int ni = 0; ni < 8; ni++)
#pragma unroll
            for (int v = 0; v < 4; v++) sacc[ni][v] = 0.0f;

#pragma unroll
        for (int ks = 0; ks < 4; ks++) {
#pragma unroll
            for (int p = 0; p < 4; p++) {
                uint32_t bf[4];
                ldsm4(bf, bK + b_lo + (uint32_t)((p * 16 * KSTR) * 2 + ks * 32));
                mma_f16(sacc[2 * p],     qfr[ks], bf[0], bf[1]);
                mma_f16(sacc[2 * p + 1], qfr[ks], bf[2], bf[3]);
            }
        }

        // ---- scale + ALiBi + causal (fp32) ----
        const bool needmask = (kt >= 2 * qt);
        float mx0 = -1e30f, mx1 = -1e30f;
#pragma unroll
        for (int ni = 0; ni < 8; ni++) {
            const int key0 = k0 + ni * 8 + 2 * qid;
            const float d0 = (float)(key0 - qg0);
            float v0 = fmaf(sacc[ni][0], 0.125f, slope * d0);
            float v1 = fmaf(sacc[ni][1], 0.125f, slope * (d0 + 1.0f));
            float v2 = fmaf(sacc[ni][2], 0.125f, slope * (d0 - 8.0f));
            float v3 = fmaf(sacc[ni][3], 0.125f, slope * (d0 - 7.0f));
            if (needmask) {
                if (key0     > qg0)     v0 = -1e30f;
                if (key0 + 1 > qg0)     v1 = -1e30f;
                if (key0     > qg0 + 8) v2 = -1e30f;
                if (key0 + 1 > qg0 + 8) v3 = -1e30f;
            }
            sacc[ni][0] = v0; sacc[ni][1] = v1;
            sacc[ni][2] = v2; sacc[ni][3] = v3;
            mx0 = fmaxf(mx0, fmaxf(v0, v1));
            mx1 = fmaxf(mx1, fmaxf(v2, v3));
        }
        mx0 = fmaxf(mx0, __shfl_xor_sync(0xffffffffu, mx0, 1));
        mx0 = fmaxf(mx0, __shfl_xor_sync(0xffffffffu, mx0, 2));
        mx1 = fmaxf(mx1, __shfl_xor_sync(0xffffffffu, mx1, 1));
        mx1 = fmaxf(mx1, __shfl_xor_sync(0xffffffffu, mx1, 2));

        const float mn0 = fmaxf(m_[0], mx0);
        const float mn1 = fmaxf(m_[1], mx1);
        const float sc0 = __expf(m_[0] - mn0);
        const float sc1 = __expf(m_[1] - mn1);
        m_[0] = mn0; m_[1] = mn1;

        float rs0 = 0.0f, rs1 = 0.0f;
#pragma unroll
        for (int ni = 0; ni < 8; ni++) {
            sacc[ni][0] = __expf(sacc[ni][0] - mn0);
            sacc[ni][1] = __expf(sacc[ni][1] - mn0);
            sacc[ni][2] = __expf(sacc[ni][2] - mn1);
            sacc[ni][3] = __expf(sacc[ni][3] - mn1);
            rs0 += sacc[ni][0] + sacc[ni][1];
            rs1 += sacc[ni][2] + sacc[ni][3];
        }
        rs0 += __shfl_xor_sync(0xffffffffu, rs0, 1);
        rs0 += __shfl_xor_sync(0xffffffffu, rs0, 2);
        rs1 += __shfl_xor_sync(0xffffffffu, rs1, 1);
        rs1 += __shfl_xor_sync(0xffffffffu, rs1, 2);
        l_[0] = l_[0] * sc0 + rs0;
        l_[1] = l_[1] * sc1 + rs1;

#pragma unroll
        for (int ni = 0; ni < 8; ni++) {
            oacc[ni][0] *= sc0; oacc[ni][1] *= sc0;
            oacc[ni][2] *= sc1; oacc[ni][3] *= sc1;
        }

        // ---- O += P @ V (P from registers: C-frag == A-frag layout) ----
#pragma unroll
        for (int kg = 0; kg < 4; kg++) {
            uint32_t pa[4];
            pa[0] = pkf16(sacc[2 * kg][0],     sacc[2 * kg][1]);
            pa[1] = pkf16(sacc[2 * kg][2],     sacc[2 * kg][3]);
            pa[2] = pkf16(sacc[2 * kg + 1][0], sacc[2 * kg + 1][1]);
            pa[3] = pkf16(sacc[2 * kg + 1][2], sacc[2 * kg + 1][3]);
#pragma unroll
            for (int dd = 0; dd < 4; dd++) {
                uint32_t vf[4];
                ldsm4t(vf, bV + v_lo +
                       (uint32_t)((kg * 16 * KSTR) * 2 + dd * 32));
                mma_f16(oacc[2 * dd],     pa, vf[0], vf[1]);
                mma_f16(oacc[2 * dd + 1], pa, vf[2], vf[3]);
            }
        }
        __syncthreads();
    }

    // ---- epilogue (fp16 y) ----
    const float inv0 = 1.0f / l_[0];
    const float inv1 = 1.0f / l_[1];
    __half* d0p = y + ((size_t)(b * SEQ + qg0)) * DMODEL + h * HDIM;
    __half* d1p = d0p + (size_t)8 * DMODEL;
#pragma unroll
    for (int ni = 0; ni < 8; ni++) {
        const int c = ni * 8 + 2 * qid;
        *(uint32_t*)(d0p + c) = pkf16(oacc[ni][0] * inv0, oacc[ni][1] * inv0);
        *(uint32_t*)(d1p + c) = pkf16(oacc[ni][2] * inv1, oacc[ni][3] * inv1);
    }
}

// ---------------------------------------------------------------------------
extern "C" void kernel_launch(void* const* d_in, const int* in_sizes, int n_in,
                              void* d_out, int out_size)
{
    const float* x   = (const float*)d_in[0];
    const float* Wq  = (const float*)d_in[2];
    const float* bq  = (const float*)d_in[3];
    const float* Wkv = (const float*)d_in[4];
    const float* bkv = (const float*)d_in[5];
    const float* Wo  = (const float*)d_in[6];
    const float* bo  = (const float*)d_in[7];
    float* out = (float*)d_out;

    void *pq, *pkv, *py;
    cudaGetSymbolAddress(&pq, g_q);
    cudaGetSymbolAddress(&pkv, g_kv);
    cudaGetSymbolAddress(&py, g_y);
    __half* qb  = (__half*)pq;
    __half* kvb = (__half*)pkv;
    __half* yb  = (__half*)py;

    const int gemm_smem = 2 * GBUFB;            // 40960 B
    cudaFuncSetAttribute(gemm_f2h,
                         cudaFuncAttributeMaxDynamicSharedMemorySize, gemm_smem);
    cudaFuncSetAttribute(gemm_h2f,
                         cudaFuncAttributeMaxDynamicSharedMemorySize, gemm_smem);

    // Q projection
    gemm_f2h<<<dim3(DMODEL / 128, MTOT / 128), 256, gemm_smem>>>(
        x, Wq, bq, qb, DMODEL, DMODEL);

    // KV projection
    gemm_f2h<<<dim3(2 * DMODEL / 128, MTOT / 128), 256, gemm_smem>>>(
        x, Wkv, bkv, kvb, 2 * DMODEL, DMODEL);

    // Attention
    const int attn_smem = 2 * ABUF_B;           // 36864 B
    cudaFuncSetAttribute(attn_mma,
                         cudaFuncAttributeMaxDynamicSharedMemorySize, attn_smem);
    attn_mma<<<dim3(SEQ / 128, NHEAD, BATCH), 256, attn_smem>>>(qb, kvb, yb);

    // Output projection
    gemm_h2f<<<dim3(DMODEL / 128, MTOT / 128), 256, gemm_smem>>>(
        yb, Wo, bo, out, DMODEL, DMODEL);
}

// round 7
// speedup vs baseline: 2.3528x; 1.1624x over previous
#include <cuda_runtime.h>
#include <cuda_fp16.h>
#include <cstdint>
#include <math.h>

#define BATCH 2
#define SEQ   2048
#define DMODEL 1024
#define NHEAD 16
#define HDIM  64
#define MTOT  (BATCH * SEQ)   // 4096

// fp16 scratch (allocation-free rule: __device__ globals)
__device__ __half g_q[(size_t)MTOT * DMODEL];        // 8 MB
__device__ __half g_kv[(size_t)MTOT * 2 * DMODEL];   // 16 MB
__device__ __half g_y[(size_t)MTOT * DMODEL];        // 8 MB
__device__ __half g_xh[(size_t)MTOT * DMODEL];       // 8 MB
__device__ __half g_wq[(size_t)DMODEL * DMODEL];     // 2 MB
__device__ __half g_wkv[(size_t)2 * DMODEL * DMODEL];// 4 MB
__device__ __half g_wo[(size_t)DMODEL * DMODEL];     // 2 MB

// ---------------------------------------------------------------------------
// helpers
// ---------------------------------------------------------------------------
__device__ __forceinline__ uint32_t smem_u32(const void* p) {
    uint32_t a;
    asm("{ .reg .u64 t; cvta.to.shared.u64 t, %1; cvt.u32.u64 %0, t; }"
        : "=r"(a) : "l"(p));
    return a;
}

__device__ __forceinline__ uint32_t pkf16(float lo, float hi) {
    uint32_t r;
    asm("cvt.rn.f16x2.f32 %0, %1, %2;" : "=r"(r) : "f"(hi), "f"(lo));
    return r;
}

__device__ __forceinline__ void mma_f16(float* c, const uint32_t* a,
                                        uint32_t b0, uint32_t b1) {
    asm volatile(
        "mma.sync.aligned.m16n8k16.row.col.f32.f16.f16.f32 "
        "{%0,%1,%2,%3}, {%4,%5,%6,%7}, {%8,%9}, {%0,%1,%2,%3};"
        : "+f"(c[0]), "+f"(c[1]), "+f"(c[2]), "+f"(c[3])
        : "r"(a[0]), "r"(a[1]), "r"(a[2]), "r"(a[3]), "r"(b0), "r"(b1));
}

__device__ __forceinline__ void ldsm4(uint32_t* r, uint32_t addr) {
    asm volatile("ldmatrix.sync.aligned.m8n8.x4.shared.b16 {%0,%1,%2,%3}, [%4];"
                 : "=r"(r[0]), "=r"(r[1]), "=r"(r[2]), "=r"(r[3]) : "r"(addr));
}

__device__ __forceinline__ void ldsm4t(uint32_t* r, uint32_t addr) {
    asm volatile("ldmatrix.sync.aligned.m8n8.x4.trans.shared.b16 {%0,%1,%2,%3}, [%4];"
                 : "=r"(r[0]), "=r"(r[1]), "=r"(r[2]), "=r"(r[3]) : "r"(addr));
}

__device__ __forceinline__ void cp16(uint32_t dst, const void* src) {
    asm volatile("cp.async.cg.shared.global [%0], [%1], 16;"
                 :: "r"(dst), "l"(src) : "memory");
}
#define CP_COMMIT() asm volatile("cp.async.commit_group;" ::: "memory")
#define CP_WAIT0()  asm volatile("cp.async.wait_group 0;" ::: "memory")
#define CP_WAIT1()  asm volatile("cp.async.wait_group 1;" ::: "memory")

__device__ __forceinline__ void st_pair(__half* C, size_t off, float v0, float v1) {
    *(uint32_t*)(C + off) = pkf16(v0, v1);
}
__device__ __forceinline__ void st_pair(float* C, size_t off, float v0, float v1) {
    float2 t; t.x = v0; t.y = v1;
    *(float2*)(C + off) = t;
}

// ---------------------------------------------------------------------------
// fp32 -> fp16 conversion (one-time pre-pass)
// ---------------------------------------------------------------------------
__global__ __launch_bounds__(256) void cvt_f2h(
    const float* __restrict__ src, __half* __restrict__ dst, int n)
{
    int i = (blockIdx.x * 256 + threadIdx.x) * 8;
    if (i < n) {
        float4 a = *(const float4*)(src + i);
        float4 b = *(const float4*)(src + i + 4);
        uint4 o;
        o.x = pkf16(a.x, a.y); o.y = pkf16(a.z, a.w);
        o.z = pkf16(b.x, b.y); o.w = pkf16(b.z, b.w);
        *(uint4*)(dst + i) = o;
    }
}

// ---------------------------------------------------------------------------
// fp16 tensor-core GEMM: C[M,N] = A[M,K] @ W[N,K]^T + bias[N]
// CTA 128(m) x 256(n), 8 warps (2m x 4n), warp tile 64x64, BK=32.
// cp.async double-buffered. smem stride 40 halfs -> conflict-free ldmatrix.
// ---------------------------------------------------------------------------
#define GAS 40                          // smem row stride in halfs (80 B)
#define ATILE_B (128 * GAS * 2)         // 10240 B
#define BTILE_B (256 * GAS * 2)         // 20480 B
#define GSTAGE_B (ATILE_B + BTILE_B)    // 30720 B per stage

template<typename OT>
__device__ __forceinline__ void gemm_body(
    const __half* __restrict__ A, const __half* __restrict__ W,
    const float* __restrict__ bias, OT* __restrict__ C,
    int N, int K, int bm, int bn, uint32_t sb)
{
    const int tid = threadIdx.x, wid = tid >> 5, lane = tid & 31;
    const int grp = lane >> 2, qid = lane & 3;
    const int rbase = (wid & 1) * 64;       // warp M offset
    const int nbase = (wid >> 1) * 64;      // warp N offset

    // loader mapping
    const int arow = tid >> 1, aseg = (tid & 1) * 16;      // A: 2 cp16/thread
    const __half* Ap = A + (size_t)(bm + arow) * K + aseg;
    const uint32_t a_sts = (uint32_t)(arow * GAS + aseg) * 2u;
    const int brow = tid;                                   // W: 4 cp16/thread
    const __half* Wp = W + (size_t)(bn + brow) * K;
    const uint32_t b_sts = (uint32_t)(brow * GAS) * 2u;

    float acc[4][8][4];
#pragma unroll
    for (int mi = 0; mi < 4; mi++)
#pragma unroll
        for (int ni = 0; ni < 8; ni++)
#pragma unroll
            for (int v = 0; v < 4; v++) acc[mi][ni][v] = 0.0f;

    const int NC = K / 32;

    // prologue: issue chunk 0 into stage 0
    {
        cp16(sb + a_sts, Ap);
        cp16(sb + a_sts + 16, Ap + 8);
        const uint32_t bst = sb + ATILE_B + b_sts;
        cp16(bst,      Wp);
        cp16(bst + 16, Wp + 8);
        cp16(bst + 32, Wp + 16);
        cp16(bst + 48, Wp + 24);
        CP_COMMIT();
    }

    const uint32_t a_lo = (uint32_t)((lane & 15) * GAS + (lane >> 4) * 8) * 2u;
    const uint32_t b_lo = (uint32_t)((((lane >> 4) & 1) * 8 + (lane & 7)) * GAS
                                     + ((lane >> 3) & 1) * 8) * 2u;

    for (int c = 0; c < NC; c++) {
        if (c + 1 < NC) {
            const uint32_t st = sb + (uint32_t)((c + 1) & 1) * GSTAGE_B;
            const __half* Ap2 = Ap + (c + 1) * 32;
            const __half* Wp2 = Wp + (c + 1) * 32;
            cp16(st + a_sts, Ap2);
            cp16(st + a_sts + 16, Ap2 + 8);
            const uint32_t bst = st + ATILE_B + b_sts;
            cp16(bst,      Wp2);
            cp16(bst + 16, Wp2 + 8);
            cp16(bst + 32, Wp2 + 16);
            cp16(bst + 48, Wp2 + 24);
            CP_COMMIT();
            CP_WAIT1();
        } else {
            CP_WAIT0();
        }
        __syncthreads();

        const uint32_t Ab = sb + (uint32_t)(c & 1) * GSTAGE_B;
        const uint32_t Bb = Ab + ATILE_B;

#pragma unroll
        for (int ks = 0; ks < 2; ks++) {
            uint32_t af[4][4];
#pragma unroll
            for (int mi = 0; mi < 4; mi++)
                ldsm4(af[mi], Ab + a_lo +
                      (uint32_t)(((rbase + mi * 16) * GAS + ks * 16) * 2));
            uint32_t bf[16];
#pragma unroll
            for (int p = 0; p < 4; p++)
                ldsm4(bf + 4 * p, Bb + b_lo +
                      (uint32_t)(((nbase + p * 16) * GAS + ks * 16) * 2));
#pragma unroll
            for (int mi = 0; mi < 4; mi++)
#pragma unroll
                for (int ni = 0; ni < 8; ni++)
                    mma_f16(acc[mi][ni], af[mi], bf[2 * ni], bf[2 * ni + 1]);
        }
        __syncthreads();    // all frag reads done before overwrite (iter c+1 issue)
    }

#pragma unroll
    for (int mi = 0; mi < 4; mi++) {
        const int row = bm + rbase + mi * 16 + grp;
#pragma unroll
        for (int ni = 0; ni < 8; ni++) {
            const int col = bn + nbase + ni * 8 + 2 * qid;
            const float2 bv = *(const float2*)(bias + col);
            st_pair(C, (size_t)row * N + col,
                    acc[mi][ni][0] + bv.x, acc[mi][ni][1] + bv.y);
            st_pair(C, (size_t)(row + 8) * N + col,
                    acc[mi][ni][2] + bv.x, acc[mi][ni][3] + bv.y);
        }
    }
}

__global__ __launch_bounds__(256) void gemm_hh(
    const __half* __restrict__ A, const __half* __restrict__ W,
    const float* __restrict__ bias, __half* __restrict__ C, int N, int K)
{
    extern __shared__ __half smh[];
    gemm_body<__half>(A, W, bias, C, N, K,
                      blockIdx.y * 128, blockIdx.x * 256, smem_u32(smh));
}

__global__ __launch_bounds__(256) void gemm_hf(
    const __half* __restrict__ A, const __half* __restrict__ W,
    const float* __restrict__ bias, float* __restrict__ C, int N, int K)
{
    extern __shared__ __half smh[];
    gemm_body<float>(A, W, bias, C, N, K,
                     blockIdx.y * 128, blockIdx.x * 256, smem_u32(smh));
}

// ---------------------------------------------------------------------------
// fp16 tensor-core flash attention (unchanged from R6 — validated).
// ---------------------------------------------------------------------------
#define KSTR 72
#define KTILE_B (64 * KSTR * 2)
#define ABUF_B (2 * KTILE_B)

__global__ __launch_bounds__(256) void attn_mma(
    const __half* __restrict__ q, const __half* __restrict__ kv,
    __half* __restrict__ y)
{
    extern __shared__ __half smh[];
    const uint32_t sb = smem_u32(smh);

    const int tid = threadIdx.x;
    const int wid = tid >> 5, lane = tid & 31;
    const int grp = lane >> 2, qid = lane & 3;
    const int qt = (int)gridDim.x - 1 - (int)blockIdx.x;
    const int h = blockIdx.y, b = blockIdx.z;
    const int q0 = qt * 128;
    const float slope = (float)(h + 1) * (1.0f / NHEAD);

    {
        const int row = tid >> 1;
        const int seg = (tid & 1) * 4;
        const __half* src = q + ((size_t)(b * SEQ + q0 + row)) * DMODEL
                            + h * HDIM + seg * 8;
        const uint32_t dst = sb + (uint32_t)(row * KSTR * 2 + seg * 16);
#pragma unroll
        for (int u = 0; u < 4; u++) cp16(dst + u * 16, src + u * 8);
    }
    CP_COMMIT();
    CP_WAIT0();
    __syncthreads();

    const uint32_t a_lo = (uint32_t)((lane & 15) * KSTR + (lane >> 4) * 8) * 2u;
    uint32_t qfr[4][4];
    {
        const uint32_t qwarp = sb + (uint32_t)(16 * wid * KSTR * 2) + a_lo;
#pragma unroll
        for (int ks = 0; ks < 4; ks++) ldsm4(qfr[ks], qwarp + ks * 32);
    }
    __syncthreads();

    const uint32_t b_lo = (uint32_t)((((lane >> 4) & 1) * 8 + (lane & 7)) * KSTR
                                     + ((lane >> 3) & 1) * 8) * 2u;
    const uint32_t v_lo = (uint32_t)(((lane & 7) + ((lane >> 3) & 1) * 8) * KSTR
                                     + (lane >> 4) * 8) * 2u;

    float m_[2] = {-1e30f, -1e30f};
    float l_[2] = {0.0f, 0.0f};
    float oacc[8][4];
#pragma unroll
    for (int ni = 0; ni < 8; ni++)
#pragma unroll
        for (int v = 0; v < 4; v++) oacc[ni][v] = 0.0f;

    const int qg0 = q0 + 16 * wid + grp;
    const int ktmax = 2 * qt + 1;

    const int krow = tid >> 2, kseg = tid & 3;
    const __half* kvbase = kv + ((size_t)(b * SEQ + krow)) * (2 * DMODEL) + h * HDIM;

    {
        const __half* src = kvbase;
        const uint32_t dK = sb + (uint32_t)(krow * KSTR * 2);
        const uint32_t dV = dK + (uint32_t)KTILE_B;
        cp16(dK + kseg * 16, src + kseg * 8);
        cp16(dK + (kseg + 4) * 16, src + (kseg + 4) * 8);
        cp16(dV + kseg * 16, src + DMODEL + kseg * 8);
        cp16(dV + (kseg + 4) * 16, src + DMODEL + (kseg + 4) * 8);
    }
    CP_COMMIT();

    for (int kt = 0; kt <= ktmax; kt++) {
        const int k0 = kt * 64;
        const uint32_t bK = sb + (uint32_t)(kt & 1) * ABUF_B;
        const uint32_t bV = bK + (uint32_t)KTILE_B;

        if (kt < ktmax) {
            const __half* src = kvbase + (size_t)(k0 + 64) * (2 * DMODEL);
            const uint32_t dK = sb + (uint32_t)((kt + 1) & 1) * ABUF_B
                                + (uint32_t)(krow * KSTR * 2);
            const uint32_t dV = dK + (uint32_t)KTILE_B;
            cp16(dK + kseg * 16, src + kseg * 8);
            cp16(dK + (kseg + 4) * 16, src + (kseg + 4) * 8);
            cp16(dV + kseg * 16, src + DMODEL + kseg * 8);
            cp16(dV + (kseg + 4) * 16, src + DMODEL + (kseg + 4) * 8);
            CP_COMMIT();
            CP_WAIT1();
        } else {
            CP_WAIT0();
        }
        __syncthreads();

        float sacc[8][4];
#pragma unroll
        for (int ni = 0; ni < 8; ni++)
#pragma unroll
            for (int v = 0; v < 4; v++) sacc[ni][v] = 0.0f;

#pragma unroll
        for (int ks = 0; ks < 4; ks++) {
#pragma unroll
            for (int p = 0; p < 4; p++) {
                uint32_t bf[4];
                ldsm4(bf, bK + b_lo + (uint32_t)((p * 16 * KSTR) * 2 + ks * 32));
                mma_f16(sacc[2 * p],     qfr[ks], bf[0], bf[1]);
                mma_f16(sacc[2 * p + 1], qfr[ks], bf[2], bf[3]);
            }
        }

        const bool needmask = (kt >= 2 * qt);
        float mx0 = -1e30f, mx1 = -1e30f;
#pragma unroll
        for (int ni = 0; ni < 8; ni++) {
            const int key0 = k0 + ni * 8 + 2 * qid;
            const float d0 = (float)(key0 - qg0);
            float v0 = fmaf(sacc[ni][0], 0.125f, slope * d0);
            float v1 = fmaf(sacc[ni][1], 0.125f, slope * (d0 + 1.0f));
            float v2 = fmaf(sacc[ni][2], 0.125f, slope * (d0 - 8.0f));
            float v3 = fmaf(sacc[ni][3], 0.125f, slope * (d0 - 7.0f));
            if (needmask) {
                if (key0     > qg0)     v0 = -1e30f;
                if (key0 + 1 > qg0)     v1 = -1e30f;
                if (key0     > qg0 + 8) v2 = -1e30f;
                if (key0 + 1 > qg0 + 8) v3 = -1e30f;
            }
            sacc[ni][0] = v0; sacc[ni][1] = v1;
            sacc[ni][2] = v2; sacc[ni][3] = v3;
            mx0 = fmaxf(mx0, fmaxf(v0, v1));
            mx1 = fmaxf(mx1, fmaxf(v2, v3));
        }
        mx0 = fmaxf(mx0, __shfl_xor_sync(0xffffffffu, mx0, 1));
        mx0 = fmaxf(mx0, __shfl_xor_sync(0xffffffffu, mx0, 2));
        mx1 = fmaxf(mx1, __shfl_xor_sync(0xffffffffu, mx1, 1));
        mx1 = fmaxf(mx1, __shfl_xor_sync(0xffffffffu, mx1, 2));

        const float mn0 = fmaxf(m_[0], mx0);
        const float mn1 = fmaxf(m_[1], mx1);
        const float sc0 = __expf(m_[0] - mn0);
        const float sc1 = __expf(m_[1] - mn1);
        m_[0] = mn0; m_[1] = mn1;

        float rs0 = 0.0f, rs1 = 0.0f;
#pragma unroll
        for (int ni = 0; ni < 8; ni++) {
            sacc[ni][0] = __expf(sacc[ni][0] - mn0);
            sacc[ni][1] = __expf(sacc[ni][1] - mn0);
            sacc[ni][2] = __expf(sacc[ni][2] - mn1);
            sacc[ni][3] = __expf(sacc[ni][3] - mn1);
            rs0 += sacc[ni][0] + sacc[ni][1];
            rs1 += sacc[ni][2] + sacc[ni][3];
        }
        rs0 += __shfl_xor_sync(0xffffffffu, rs0, 1);
        rs0 += __shfl_xor_sync(0xffffffffu, rs0, 2);
        rs1 += __shfl_xor_sync(0xffffffffu, rs1, 1);
        rs1 += __shfl_xor_sync(0xffffffffu, rs1, 2);
        l_[0] = l_[0] * sc0 + rs0;
        l_[1] = l_[1] * sc1 + rs1;

#pragma unroll
        for (int ni = 0; ni < 8; ni++) {
            oacc[ni][0] *= sc0; oacc[ni][1] *= sc0;
            oacc[ni][2] *= sc1; oacc[ni][3] *= sc1;
        }

#pragma unroll
        for (int kg = 0; kg < 4; kg++) {
            uint32_t pa[4];
            pa[0] = pkf16(sacc[2 * kg][0],     sacc[2 * kg][1]);
            pa[1] = pkf16(sacc[2 * kg][2],     sacc[2 * kg][3]);
            pa[2] = pkf16(sacc[2 * kg + 1][0], sacc[2 * kg + 1][1]);
            pa[3] = pkf16(sacc[2 * kg + 1][2], sacc[2 * kg + 1][3]);
#pragma unroll
            for (int dd = 0; dd < 4; dd++) {
                uint32_t vf[4];
                ldsm4t(vf, bV + v_lo +
                       (uint32_t)((kg * 16 * KSTR) * 2 + dd * 32));
                mma_f16(oacc[2 * dd],     pa, vf[0], vf[1]);
                mma_f16(oacc[2 * dd + 1], pa, vf[2], vf[3]);
            }
        }
        __syncthreads();
    }

    const float inv0 = 1.0f / l_[0];
    const float inv1 = 1.0f / l_[1];
    __half* d0p = y + ((size_t)(b * SEQ + qg0)) * DMODEL + h * HDIM;
    __half* d1p = d0p + (size_t)8 * DMODEL;
#pragma unroll
    for (int ni = 0; ni < 8; ni++) {
        const int c = ni * 8 + 2 * qid;
        *(uint32_t*)(d0p + c) = pkf16(oacc[ni][0] * inv0, oacc[ni][1] * inv0);
        *(uint32_t*)(d1p + c) = pkf16(oacc[ni][2] * inv1, oacc[ni][3] * inv1);
    }
}

// ---------------------------------------------------------------------------
extern "C" void kernel_launch(void* const* d_in, const int* in_sizes, int n_in,
                              void* d_out, int out_size)
{
    const float* x   = (const float*)d_in[0];
    const float* Wq  = (const float*)d_in[2];
    const float* bq  = (const float*)d_in[3];
    const float* Wkv = (const float*)d_in[4];
    const float* bkv = (const float*)d_in[5];
    const float* Wo  = (const float*)d_in[6];
    const float* bo  = (const float*)d_in[7];
    float* out = (float*)d_out;

    void *pq, *pkv, *py, *pxh, *pwq, *pwkv, *pwo;
    cudaGetSymbolAddress(&pq, g_q);
    cudaGetSymbolAddress(&pkv, g_kv);
    cudaGetSymbolAddress(&py, g_y);
    cudaGetSymbolAddress(&pxh, g_xh);
    cudaGetSymbolAddress(&pwq, g_wq);
    cudaGetSymbolAddress(&pwkv, g_wkv);
    cudaGetSymbolAddress(&pwo, g_wo);
    __half* qb   = (__half*)pq;
    __half* kvb  = (__half*)pkv;
    __half* yb   = (__half*)py;
    __half* xh   = (__half*)pxh;
    __half* wqh  = (__half*)pwq;
    __half* wkvh = (__half*)pwkv;
    __half* woh  = (__half*)pwo;

    // pre-convert inputs/weights to fp16
    const int nx = MTOT * DMODEL;
    const int nw = DMODEL * DMODEL;
    cvt_f2h<<<nx / 2048, 256>>>(x, xh, nx);
    cvt_f2h<<<nw / 2048, 256>>>(Wq, wqh, nw);
    cvt_f2h<<<2 * nw / 2048, 256>>>(Wkv, wkvh, 2 * nw);
    cvt_f2h<<<nw / 2048, 256>>>(Wo, woh, nw);

    const int gemm_smem = 2 * GSTAGE_B;         // 61440 B
    cudaFuncSetAttribute(gemm_hh,
                         cudaFuncAttributeMaxDynamicSharedMemorySize, gemm_smem);
    cudaFuncSetAttribute(gemm_hf,
                         cudaFuncAttributeMaxDynamicSharedMemorySize, gemm_smem);

    // Q projection
    gemm_hh<<<dim3(DMODEL / 256, MTOT / 128), 256, gemm_smem>>>(
        xh, wqh, bq, qb, DMODEL, DMODEL);

    // KV projection
    gemm_hh<<<dim3(2 * DMODEL / 256, MTOT / 128), 256, gemm_smem>>>(
        xh, wkvh, bkv, kvb, 2 * DMODEL, DMODEL);

    // Attention
    const int attn_smem = 2 * ABUF_B;           // 36864 B
    cudaFuncSetAttribute(attn_mma,
                         cudaFuncAttributeMaxDynamicSharedMemorySize, attn_smem);
    attn_mma<<<dim3(SEQ / 128, NHEAD, BATCH), 256, attn_smem>>>(qb, kvb, yb);

    // Output projection
    gemm_hf<<<dim3(DMODEL / 256, MTOT / 128), 256, gemm_smem>>>(
        yb, woh, bo, out, DMODEL, DMODEL);
}

// round 8
// speedup vs baseline: 2.4584x; 1.0448x over previous
#include <cuda_runtime.h>
#include <cuda_fp16.h>
#include <cstdint>
#include <math.h>

#define BATCH 2
#define SEQ   2048
#define DMODEL 1024
#define NHEAD 16
#define HDIM  64
#define MTOT  (BATCH * SEQ)   // 4096

// fp16 scratch (allocation-free rule: __device__ globals)
__device__ __half g_q[(size_t)MTOT * DMODEL];
__device__ __half g_kv[(size_t)MTOT * 2 * DMODEL];
__device__ __half g_y[(size_t)MTOT * DMODEL];
__device__ __half g_xh[(size_t)MTOT * DMODEL];
__device__ __half g_wq[(size_t)DMODEL * DMODEL];
__device__ __half g_wkv[(size_t)2 * DMODEL * DMODEL];
__device__ __half g_wo[(size_t)DMODEL * DMODEL];

// ---------------------------------------------------------------------------
// helpers
// ---------------------------------------------------------------------------
__device__ __forceinline__ uint32_t smem_u32(const void* p) {
    uint32_t a;
    asm("{ .reg .u64 t; cvta.to.shared.u64 t, %1; cvt.u32.u64 %0, t; }"
        : "=r"(a) : "l"(p));
    return a;
}

__device__ __forceinline__ uint32_t pkf16(float lo, float hi) {
    uint32_t r;
    asm("cvt.rn.f16x2.f32 %0, %1, %2;" : "=r"(r) : "f"(hi), "f"(lo));
    return r;
}

__device__ __forceinline__ float ex2f(float x) {
    float y;
    asm("ex2.approx.f32 %0, %1;" : "=f"(y) : "f"(x));
    return y;
}

__device__ __forceinline__ void mma_f16(float* c, const uint32_t* a,
                                        uint32_t b0, uint32_t b1) {
    asm volatile(
        "mma.sync.aligned.m16n8k16.row.col.f32.f16.f16.f32 "
        "{%0,%1,%2,%3}, {%4,%5,%6,%7}, {%8,%9}, {%0,%1,%2,%3};"
        : "+f"(c[0]), "+f"(c[1]), "+f"(c[2]), "+f"(c[3])
        : "r"(a[0]), "r"(a[1]), "r"(a[2]), "r"(a[3]), "r"(b0), "r"(b1));
}

__device__ __forceinline__ void ldsm4(uint32_t* r, uint32_t addr) {
    asm volatile("ldmatrix.sync.aligned.m8n8.x4.shared.b16 {%0,%1,%2,%3}, [%4];"
                 : "=r"(r[0]), "=r"(r[1]), "=r"(r[2]), "=r"(r[3]) : "r"(addr));
}

__device__ __forceinline__ void ldsm4t(uint32_t* r, uint32_t addr) {
    asm volatile("ldmatrix.sync.aligned.m8n8.x4.trans.shared.b16 {%0,%1,%2,%3}, [%4];"
                 : "=r"(r[0]), "=r"(r[1]), "=r"(r[2]), "=r"(r[3]) : "r"(addr));
}

__device__ __forceinline__ void cp16(uint32_t dst, const void* src) {
    asm volatile("cp.async.cg.shared.global [%0], [%1], 16;"
                 :: "r"(dst), "l"(src) : "memory");
}
#define CP_COMMIT() asm volatile("cp.async.commit_group;" ::: "memory")
#define CP_WAIT0()  asm volatile("cp.async.wait_group 0;" ::: "memory")
#define CP_WAIT1()  asm volatile("cp.async.wait_group 1;" ::: "memory")
#define CP_WAIT2()  asm volatile("cp.async.wait_group 2;" ::: "memory")

__device__ __forceinline__ void st_pair(__half* C, size_t off, float v0, float v1) {
    *(uint32_t*)(C + off) = pkf16(v0, v1);
}
__device__ __forceinline__ void st_pair(float* C, size_t off, float v0, float v1) {
    float2 t; t.x = v0; t.y = v1;
    *(float2*)(C + off) = t;
}

// ---------------------------------------------------------------------------
// fused fp32 -> fp16 conversion of x, Wq, Wkv, Wo (one launch)
// ---------------------------------------------------------------------------
#define NX (MTOT * DMODEL)      // 4194304
#define NW (DMODEL * DMODEL)    // 1048576

__global__ __launch_bounds__(256) void cvt_all(
    const float* __restrict__ x, const float* __restrict__ wq,
    const float* __restrict__ wkv, const float* __restrict__ wo,
    __half* __restrict__ xh, __half* __restrict__ wqh,
    __half* __restrict__ wkvh, __half* __restrict__ woh)
{
    int i = (blockIdx.x * 256 + threadIdx.x) * 8;
    const float* src;
    __half* dst;
    if (i < NX)                { src = x + i;                 dst = xh + i; }
    else if (i < NX + NW)      { src = wq + (i - NX);         dst = wqh + (i - NX); }
    else if (i < NX + 3 * NW)  { src = wkv + (i - NX - NW);   dst = wkvh + (i - NX - NW); }
    else                       { src = wo + (i - NX - 3 * NW); dst = woh + (i - NX - 3 * NW); }
    float4 a = *(const float4*)(src);
    float4 b = *(const float4*)(src + 4);
    uint4 o;
    o.x = pkf16(a.x, a.y); o.y = pkf16(a.z, a.w);
    o.z = pkf16(b.x, b.y); o.w = pkf16(b.z, b.w);
    *(uint4*)(dst) = o;
}

// ---------------------------------------------------------------------------
// fp16 tensor-core GEMM: C[M,N] = A[M,K] @ W[N,K]^T + bias[N], K = 1024 fixed.
// CTA 128(m) x 256(n), 8 warps (2m x 4n), warp tile 64x64, BK=32.
// 4-stage cp.async pipeline, ONE __syncthreads per chunk.
// ---------------------------------------------------------------------------
#define GAS 40                          // smem row stride in halfs (80 B)
#define ATILE_B (128 * GAS * 2)         // 10240 B
#define BTILE_B (256 * GAS * 2)         // 20480 B
#define GSTAGE_B (ATILE_B + BTILE_B)    // 30720 B per stage
#define GNC 32                          // K / 32

template<typename OT>
__device__ __forceinline__ void gemm_body(
    const __half* __restrict__ A, const __half* __restrict__ W,
    const float* __restrict__ bias, OT* __restrict__ C,
    int N, int bm, int bn, uint32_t sb)
{
    const int K = DMODEL;
    const int tid = threadIdx.x, wid = tid >> 5, lane = tid & 31;
    const int grp = lane >> 2, qid = lane & 3;
    const int rbase = (wid & 1) * 64;
    const int nbase = (wid >> 1) * 64;

    const int arow = tid >> 1, aseg = (tid & 1) * 16;
    const __half* Ap = A + (size_t)(bm + arow) * K + aseg;
    const uint32_t a_sts = (uint32_t)(arow * GAS + aseg) * 2u;
    const int brow = tid;
    const __half* Wp = W + (size_t)(bn + brow) * K;
    const uint32_t b_sts = (uint32_t)(brow * GAS) * 2u;

    float acc[4][8][4];
#pragma unroll
    for (int mi = 0; mi < 4; mi++)
#pragma unroll
        for (int ni = 0; ni < 8; ni++)
#pragma unroll
            for (int v = 0; v < 4; v++) acc[mi][ni][v] = 0.0f;

    // prologue: issue chunks 0,1,2 into stages 0,1,2
#pragma unroll
    for (int s = 0; s < 3; s++) {
        const uint32_t st = sb + (uint32_t)s * GSTAGE_B;
        cp16(st + a_sts, Ap + s * 32);
        cp16(st + a_sts + 16, Ap + s * 32 + 8);
        const uint32_t bst = st + ATILE_B + b_sts;
        cp16(bst,      Wp + s * 32);
        cp16(bst + 16, Wp + s * 32 + 8);
        cp16(bst + 32, Wp + s * 32 + 16);
        cp16(bst + 48, Wp + s * 32 + 24);
        CP_COMMIT();
    }

    const uint32_t a_lo = (uint32_t)((lane & 15) * GAS + (lane >> 4) * 8) * 2u;
    const uint32_t b_lo = (uint32_t)((((lane >> 4) & 1) * 8 + (lane & 7)) * GAS
                                     + ((lane >> 3) & 1) * 8) * 2u;

    for (int c = 0; c < GNC; c++) {
        CP_WAIT2();            // chunk c resident (c+1, c+2 may be in flight)
        __syncthreads();       // also: everyone done computing chunk c-1

        if (c + 3 < GNC) {     // issue chunk c+3 into stage (c+3)&3
            const uint32_t st = sb + (uint32_t)((c + 3) & 3) * GSTAGE_B;
            const __half* Ap2 = Ap + (c + 3) * 32;
            const __half* Wp2 = Wp + (c + 3) * 32;
            cp16(st + a_sts, Ap2);
            cp16(st + a_sts + 16, Ap2 + 8);
            const uint32_t bst = st + ATILE_B + b_sts;
            cp16(bst,      Wp2);
            cp16(bst + 16, Wp2 + 8);
            cp16(bst + 32, Wp2 + 16);
            cp16(bst + 48, Wp2 + 24);
        }
        CP_COMMIT();           // empty group at tail keeps wait-count uniform

        const uint32_t Ab = sb + (uint32_t)(c & 3) * GSTAGE_B;
        const uint32_t Bb = Ab + ATILE_B;

#pragma unroll
        for (int ks = 0; ks < 2; ks++) {
            uint32_t af[4][4];
#pragma unroll
            for (int mi = 0; mi < 4; mi++)
                ldsm4(af[mi], Ab + a_lo +
                      (uint32_t)(((rbase + mi * 16) * GAS + ks * 16) * 2));
            uint32_t bf[16];
#pragma unroll
            for (int p = 0; p < 4; p++)
                ldsm4(bf + 4 * p, Bb + b_lo +
                      (uint32_t)(((nbase + p * 16) * GAS + ks * 16) * 2));
#pragma unroll
            for (int mi = 0; mi < 4; mi++)
#pragma unroll
                for (int ni = 0; ni < 8; ni++)
                    mma_f16(acc[mi][ni], af[mi], bf[2 * ni], bf[2 * ni + 1]);
        }
    }

#pragma unroll
    for (int mi = 0; mi < 4; mi++) {
        const int row = bm + rbase + mi * 16 + grp;
#pragma unroll
        for (int ni = 0; ni < 8; ni++) {
            const int col = bn + nbase + ni * 8 + 2 * qid;
            const float2 bv = *(const float2*)(bias + col);
            st_pair(C, (size_t)row * N + col,
                    acc[mi][ni][0] + bv.x, acc[mi][ni][1] + bv.y);
            st_pair(C, (size_t)(row + 8) * N + col,
                    acc[mi][ni][2] + bv.x, acc[mi][ni][3] + bv.y);
        }
    }
}

__global__ __launch_bounds__(256) void gemm_hh(
    const __half* __restrict__ A, const __half* __restrict__ W,
    const float* __restrict__ bias, __half* __restrict__ C, int N)
{
    extern __shared__ __half smh[];
    gemm_body<__half>(A, W, bias, C, N,
                      blockIdx.y * 128, blockIdx.x * 256, smem_u32(smh));
}

__global__ __launch_bounds__(256) void gemm_hf(
    const __half* __restrict__ A, const __half* __restrict__ W,
    const float* __restrict__ bias, float* __restrict__ C, int N)
{
    extern __shared__ __half smh[];
    gemm_body<float>(A, W, bias, C, N,
                     blockIdx.y * 128, blockIdx.x * 256, smem_u32(smh));
}

// ---------------------------------------------------------------------------
// fp16 tensor-core flash attention, ALiBi + causal, exp2-domain softmax.
// CTA: 128 queries x head; 8 warps x 16 rows; 64-key tiles; 3-stage cp.async.
// ---------------------------------------------------------------------------
#define KSTR 72
#define KTILE_B (64 * KSTR * 2)     // 9216 B
#define ABUF_B (2 * KTILE_B)        // 18432 B per stage (K+V)

__global__ __launch_bounds__(256) void attn_mma(
    const __half* __restrict__ q, const __half* __restrict__ kv,
    __half* __restrict__ y)
{
    extern __shared__ __half smh[];
    const uint32_t sb = smem_u32(smh);

    const int tid = threadIdx.x;
    const int wid = tid >> 5, lane = tid & 31;
    const int grp = lane >> 2, qid = lane & 3;
    const int qt = (int)gridDim.x - 1 - (int)blockIdx.x;
    const int h = blockIdx.y, b = blockIdx.z;
    const int q0 = qt * 128;
    const float L2E = 1.4426950408889634f;
    const float sscale = 0.125f * L2E;
    const float slope2 = (float)(h + 1) * (1.0f / NHEAD) * L2E;

    // ---- stage Q tile into stage-0 buffer, extract frags ----
    {
        const int row = tid >> 1;
        const int seg = (tid & 1) * 4;
        const __half* src = q + ((size_t)(b * SEQ + q0 + row)) * DMODEL
                            + h * HDIM + seg * 8;
        const uint32_t dst = sb + (uint32_t)(row * KSTR * 2 + seg * 16);
#pragma unroll
        for (int u = 0; u < 4; u++) cp16(dst + u * 16, src + u * 8);
    }
    CP_COMMIT();
    CP_WAIT0();
    __syncthreads();

    const uint32_t a_lo = (uint32_t)((lane & 15) * KSTR + (lane >> 4) * 8) * 2u;
    uint32_t qfr[4][4];
    {
        const uint32_t qwarp = sb + (uint32_t)(16 * wid * KSTR * 2) + a_lo;
#pragma unroll
        for (int ks = 0; ks < 4; ks++) ldsm4(qfr[ks], qwarp + ks * 32);
    }
    __syncthreads();

    const uint32_t b_lo = (uint32_t)((((lane >> 4) & 1) * 8 + (lane & 7)) * KSTR
                                     + ((lane >> 3) & 1) * 8) * 2u;
    const uint32_t v_lo = (uint32_t)(((lane & 7) + ((lane >> 3) & 1) * 8) * KSTR
                                     + (lane >> 4) * 8) * 2u;

    float m_[2] = {-1e30f, -1e30f};
    float l_[2] = {0.0f, 0.0f};
    float oacc[8][4];
#pragma unroll
    for (int ni = 0; ni < 8; ni++)
#pragma unroll
        for (int v = 0; v < 4; v++) oacc[ni][v] = 0.0f;

    const int qg0 = q0 + 16 * wid + grp;
    const int ktmax = 2 * qt + 1;

    const int krow = tid >> 2, kseg = tid & 3;
    const __half* kvbase = kv + ((size_t)(b * SEQ + krow)) * (2 * DMODEL) + h * HDIM;

    // prologue: issue kt 0 and 1 into stages 0, 1
#pragma unroll
    for (int s = 0; s < 2; s++) {
        if (s <= ktmax) {
            const __half* src = kvbase + (size_t)(s * 64) * (2 * DMODEL);
            const uint32_t dK = sb + (uint32_t)s * ABUF_B + (uint32_t)(krow * KSTR * 2);
            const uint32_t dV = dK + (uint32_t)KTILE_B;
            cp16(dK + kseg * 16, src + kseg * 8);
            cp16(dK + (kseg + 4) * 16, src + (kseg + 4) * 8);
            cp16(dV + kseg * 16, src + DMODEL + kseg * 8);
            cp16(dV + (kseg + 4) * 16, src + DMODEL + (kseg + 4) * 8);
        }
        CP_COMMIT();
    }

    int st_c = 0, st_n = 2;    // stage of kt, stage for kt+2
    for (int kt = 0; kt <= ktmax; kt++) {
        const int k0 = kt * 64;

        CP_WAIT1();            // kt resident
        __syncthreads();       // all warps done with kt-1's buffers

        if (kt + 2 <= ktmax) { // issue kt+2 into st_n
            const __half* src = kvbase + (size_t)(k0 + 128) * (2 * DMODEL);
            const uint32_t dK = sb + (uint32_t)st_n * ABUF_B
                                + (uint32_t)(krow * KSTR * 2);
            const uint32_t dV = dK + (uint32_t)KTILE_B;
            cp16(dK + kseg * 16, src + kseg * 8);
            cp16(dK + (kseg + 4) * 16, src + (kseg + 4) * 8);
            cp16(dV + kseg * 16, src + DMODEL + kseg * 8);
            cp16(dV + (kseg + 4) * 16, src + DMODEL + (kseg + 4) * 8);
        }
        CP_COMMIT();

        const uint32_t bK = sb + (uint32_t)st_c * ABUF_B;
        const uint32_t bV = bK + (uint32_t)KTILE_B;
        st_c = (st_c == 2) ? 0 : st_c + 1;
        st_n = (st_n == 2) ? 0 : st_n + 1;

        // ---- S = Q @ K^T ----
        float sacc[8][4];
#pragma unroll
        for (int ni = 0; ni < 8; ni++)
#pragma unroll
            for (int v = 0; v < 4; v++) sacc[ni][v] = 0.0f;

#pragma unroll
        for (int ks = 0; ks < 4; ks++) {
#pragma unroll
            for (int p = 0; p < 4; p++) {
                uint32_t bf[4];
                ldsm4(bf, bK + b_lo + (uint32_t)((p * 16 * KSTR) * 2 + ks * 32));
                mma_f16(sacc[2 * p],     qfr[ks], bf[0], bf[1]);
                mma_f16(sacc[2 * p + 1], qfr[ks], bf[2], bf[3]);
            }
        }

        // ---- scale + ALiBi + causal (log2 domain) ----
        const bool needmask = (kt >= 2 * qt);
        float mx0 = -1e30f, mx1 = -1e30f;
#pragma unroll
        for (int ni = 0; ni < 8; ni++) {
            const int key0 = k0 + ni * 8 + 2 * qid;
            const float d0 = (float)(key0 - qg0);
            float v0 = fmaf(sacc[ni][0], sscale, slope2 * d0);
            float v1 = fmaf(sacc[ni][1], sscale, slope2 * (d0 + 1.0f));
            float v2 = fmaf(sacc[ni][2], sscale, slope2 * (d0 - 8.0f));
            float v3 = fmaf(sacc[ni][3], sscale, slope2 * (d0 - 7.0f));
            if (needmask) {
                if (key0     > qg0)     v0 = -1e30f;
                if (key0 + 1 > qg0)     v1 = -1e30f;
                if (key0     > qg0 + 8) v2 = -1e30f;
                if (key0 + 1 > qg0 + 8) v3 = -1e30f;
            }
            sacc[ni][0] = v0; sacc[ni][1] = v1;
            sacc[ni][2] = v2; sacc[ni][3] = v3;
            mx0 = fmaxf(mx0, fmaxf(v0, v1));
            mx1 = fmaxf(mx1, fmaxf(v2, v3));
        }
        mx0 = fmaxf(mx0, __shfl_xor_sync(0xffffffffu, mx0, 1));
        mx0 = fmaxf(mx0, __shfl_xor_sync(0xffffffffu, mx0, 2));
        mx1 = fmaxf(mx1, __shfl_xor_sync(0xffffffffu, mx1, 1));
        mx1 = fmaxf(mx1, __shfl_xor_sync(0xffffffffu, mx1, 2));

        const float mn0 = fmaxf(m_[0], mx0);
        const float mn1 = fmaxf(m_[1], mx1);
        const float sc0 = ex2f(m_[0] - mn0);
        const float sc1 = ex2f(m_[1] - mn1);
        m_[0] = mn0; m_[1] = mn1;

        float rs0 = 0.0f, rs1 = 0.0f;
#pragma unroll
        for (int ni = 0; ni < 8; ni++) {
            sacc[ni][0] = ex2f(sacc[ni][0] - mn0);
            sacc[ni][1] = ex2f(sacc[ni][1] - mn0);
            sacc[ni][2] = ex2f(sacc[ni][2] - mn1);
            sacc[ni][3] = ex2f(sacc[ni][3] - mn1);
            rs0 += sacc[ni][0] + sacc[ni][1];
            rs1 += sacc[ni][2] + sacc[ni][3];
        }
        rs0 += __shfl_xor_sync(0xffffffffu, rs0, 1);
        rs0 += __shfl_xor_sync(0xffffffffu, rs0, 2);
        rs1 += __shfl_xor_sync(0xffffffffu, rs1, 1);
        rs1 += __shfl_xor_sync(0xffffffffu, rs1, 2);
        l_[0] = l_[0] * sc0 + rs0;
        l_[1] = l_[1] * sc1 + rs1;

#pragma unroll
        for (int ni = 0; ni < 8; ni++) {
            oacc[ni][0] *= sc0; oacc[ni][1] *= sc0;
            oacc[ni][2] *= sc1; oacc[ni][3] *= sc1;
        }

        // ---- O += P @ V (P in registers) ----
#pragma unroll
        for (int kg = 0; kg < 4; kg++) {
            uint32_t pa[4];
            pa[0] = pkf16(sacc[2 * kg][0],     sacc[2 * kg][1]);
            pa[1] = pkf16(sacc[2 * kg][2],     sacc[2 * kg][3]);
            pa[2] = pkf16(sacc[2 * kg + 1][0], sacc[2 * kg + 1][1]);
            pa[3] = pkf16(sacc[2 * kg + 1][2], sacc[2 * kg + 1][3]);
#pragma unroll
            for (int dd = 0; dd < 4; dd++) {
                uint32_t vf[4];
                ldsm4t(vf, bV + v_lo +
                       (uint32_t)((kg * 16 * KSTR) * 2 + dd * 32));
                mma_f16(oacc[2 * dd],     pa, vf[0], vf[1]);
                mma_f16(oacc[2 * dd + 1], pa, vf[2], vf[3]);
            }
        }
    }

    const float inv0 = 1.0f / l_[0];
    const float inv1 = 1.0f / l_[1];
    __half* d0p = y + ((size_t)(b * SEQ + qg0)) * DMODEL + h * HDIM;
    __half* d1p = d0p + (size_t)8 * DMODEL;
#pragma unroll
    for (int ni = 0; ni < 8; ni++) {
        const int c = ni * 8 + 2 * qid;
        *(uint32_t*)(d0p + c) = pkf16(oacc[ni][0] * inv0, oacc[ni][1] * inv0);
        *(uint32_t*)(d1p + c) = pkf16(oacc[ni][2] * inv1, oacc[ni][3] * inv1);
    }
}

// ---------------------------------------------------------------------------
extern "C" void kernel_launch(void* const* d_in, const int* in_sizes, int n_in,
                              void* d_out, int out_size)
{
    const float* x   = (const float*)d_in[0];
    const float* Wq  = (const float*)d_in[2];
    const float* bq  = (const float*)d_in[3];
    const float* Wkv = (const float*)d_in[4];
    const float* bkv = (const float*)d_in[5];
    const float* Wo  = (const float*)d_in[6];
    const float* bo  = (const float*)d_in[7];
    float* out = (float*)d_out;

    void *pq, *pkv, *py, *pxh, *pwq, *pwkv, *pwo;
    cudaGetSymbolAddress(&pq, g_q);
    cudaGetSymbolAddress(&pkv, g_kv);
    cudaGetSymbolAddress(&py, g_y);
    cudaGetSymbolAddress(&pxh, g_xh);
    cudaGetSymbolAddress(&pwq, g_wq);
    cudaGetSymbolAddress(&pwkv, g_wkv);
    cudaGetSymbolAddress(&pwo, g_wo);
    __half* qb   = (__half*)pq;
    __half* kvb  = (__half*)pkv;
    __half* yb   = (__half*)py;
    __half* xh   = (__half*)pxh;
    __half* wqh  = (__half*)pwq;
    __half* wkvh = (__half*)pwkv;
    __half* woh  = (__half*)pwo;

    // fused fp16 conversion: (NX + 4*NW) / 8 elements per thread / 256
    cvt_all<<<(NX + 4 * NW) / 2048, 256>>>(x, Wq, Wkv, Wo, xh, wqh, wkvh, woh);

    const int gemm_smem = 4 * GSTAGE_B;         // 122880 B
    cudaFuncSetAttribute(gemm_hh,
                         cudaFuncAttributeMaxDynamicSharedMemorySize, gemm_smem);
    cudaFuncSetAttribute(gemm_hf,
                         cudaFuncAttributeMaxDynamicSharedMemorySize, gemm_smem);

    // Q projection
    gemm_hh<<<dim3(DMODEL / 256, MTOT / 128), 256, gemm_smem>>>(
        xh, wqh, bq, qb, DMODEL);

    // KV projection
    gemm_hh<<<dim3(2 * DMODEL / 256, MTOT / 128), 256, gemm_smem>>>(
        xh, wkvh, bkv, kvb, 2 * DMODEL);

    // Attention
    const int attn_smem = 3 * ABUF_B;           // 55296 B
    cudaFuncSetAttribute(attn_mma,
                         cudaFuncAttributeMaxDynamicSharedMemorySize, attn_smem);
    attn_mma<<<dim3(SEQ / 128, NHEAD, BATCH), 256, attn_smem>>>(qb, kvb, yb);

    // Output projection
    gemm_hf<<<dim3(DMODEL / 256, MTOT / 128), 256, gemm_smem>>>(
        yb, woh, bo, out, DMODEL);
}

// round 9
// speedup vs baseline: 2.8091x; 1.1427x over previous
#include <cuda_runtime.h>
#include <cuda_fp16.h>
#include <cstdint>
#include <math.h>

#define BATCH 2
#define SEQ   2048
#define DMODEL 1024
#define NHEAD 16
#define HDIM  64
#define MTOT  (BATCH * SEQ)   // 4096

// fp16 scratch (allocation-free rule: __device__ globals)
__device__ __half g_q[(size_t)MTOT * DMODEL];
__device__ __half g_kv[(size_t)MTOT * 2 * DMODEL];
__device__ __half g_y[(size_t)MTOT * DMODEL];
__device__ __half g_xh[(size_t)MTOT * DMODEL];
__device__ __half g_wq[(size_t)DMODEL * DMODEL];
__device__ __half g_wkv[(size_t)2 * DMODEL * DMODEL];
__device__ __half g_wo[(size_t)DMODEL * DMODEL];

// ---------------------------------------------------------------------------
// helpers
// ---------------------------------------------------------------------------
__device__ __forceinline__ uint32_t smem_u32(const void* p) {
    uint32_t a;
    asm("{ .reg .u64 t; cvta.to.shared.u64 t, %1; cvt.u32.u64 %0, t; }"
        : "=r"(a) : "l"(p));
    return a;
}

__device__ __forceinline__ uint32_t pkf16(float lo, float hi) {
    uint32_t r;
    asm("cvt.rn.f16x2.f32 %0, %1, %2;" : "=r"(r) : "f"(hi), "f"(lo));
    return r;
}

__device__ __forceinline__ float ex2f(float x) {
    float y;
    asm("ex2.approx.f32 %0, %1;" : "=f"(y) : "f"(x));
    return y;
}

__device__ __forceinline__ uint32_t ex2h2(uint32_t x) {
    uint32_t y;
    asm("ex2.approx.f16x2 %0, %1;" : "=r"(y) : "r"(x));
    return y;
}

__device__ __forceinline__ void mma_f16(float* c, const uint32_t* a,
                                        uint32_t b0, uint32_t b1) {
    asm volatile(
        "mma.sync.aligned.m16n8k16.row.col.f32.f16.f16.f32 "
        "{%0,%1,%2,%3}, {%4,%5,%6,%7}, {%8,%9}, {%0,%1,%2,%3};"
        : "+f"(c[0]), "+f"(c[1]), "+f"(c[2]), "+f"(c[3])
        : "r"(a[0]), "r"(a[1]), "r"(a[2]), "r"(a[3]), "r"(b0), "r"(b1));
}

__device__ __forceinline__ void ldsm4(uint32_t* r, uint32_t addr) {
    asm volatile("ldmatrix.sync.aligned.m8n8.x4.shared.b16 {%0,%1,%2,%3}, [%4];"
                 : "=r"(r[0]), "=r"(r[1]), "=r"(r[2]), "=r"(r[3]) : "r"(addr));
}

__device__ __forceinline__ void ldsm4t(uint32_t* r, uint32_t addr) {
    asm volatile("ldmatrix.sync.aligned.m8n8.x4.trans.shared.b16 {%0,%1,%2,%3}, [%4];"
                 : "=r"(r[0]), "=r"(r[1]), "=r"(r[2]), "=r"(r[3]) : "r"(addr));
}

__device__ __forceinline__ void ldsm2t(uint32_t* r, uint32_t addr) {
    asm volatile("ldmatrix.sync.aligned.m8n8.x2.trans.shared.b16 {%0,%1}, [%2];"
                 : "=r"(r[0]), "=r"(r[1]) : "r"(addr));
}

__device__ __forceinline__ void cp16(uint32_t dst, const void* src) {
    asm volatile("cp.async.cg.shared.global [%0], [%1], 16;"
                 :: "r"(dst), "l"(src) : "memory");
}
#define CP_COMMIT() asm volatile("cp.async.commit_group;" ::: "memory")
#define CP_WAIT0()  asm volatile("cp.async.wait_group 0;" ::: "memory")
#define CP_WAIT1()  asm volatile("cp.async.wait_group 1;" ::: "memory")

__device__ __forceinline__ void st_pair(__half* C, size_t off, float v0, float v1) {
    *(uint32_t*)(C + off) = pkf16(v0, v1);
}
__device__ __forceinline__ void st_pair(float* C, size_t off, float v0, float v1) {
    float2 t; t.x = v0; t.y = v1;
    *(float2*)(C + off) = t;
}

// ---------------------------------------------------------------------------
// fused fp32 -> fp16 conversion, 4 loads in flight per thread
// ---------------------------------------------------------------------------
#define NX (MTOT * DMODEL)      // 4194304
#define NW (DMODEL * DMODEL)    // 1048576
#define CVT_TOTAL (NX + 4 * NW) // 8388608
#define CVT_HALF (CVT_TOTAL / 2)

__device__ __forceinline__ void cvt_sel(
    int i, const float* x, const float* wq, const float* wkv, const float* wo,
    __half* xh, __half* wqh, __half* wkvh, __half* woh,
    const float** s, __half** d)
{
    if (i < NX)               { *s = x + i;                  *d = xh + i; }
    else if (i < NX + NW)     { *s = wq + (i - NX);          *d = wqh + (i - NX); }
    else if (i < NX + 3 * NW) { *s = wkv + (i - NX - NW);    *d = wkvh + (i - NX - NW); }
    else                      { *s = wo + (i - NX - 3 * NW); *d = woh + (i - NX - 3 * NW); }
}

__global__ __launch_bounds__(256) void cvt_all(
    const float* __restrict__ x, const float* __restrict__ wq,
    const float* __restrict__ wkv, const float* __restrict__ wo,
    __half* __restrict__ xh, __half* __restrict__ wqh,
    __half* __restrict__ wkvh, __half* __restrict__ woh)
{
    int i0 = (blockIdx.x * 256 + threadIdx.x) * 8;
    const float *s0, *s1;
    __half *d0, *d1;
    cvt_sel(i0, x, wq, wkv, wo, xh, wqh, wkvh, woh, &s0, &d0);
    cvt_sel(i0 + CVT_HALF, x, wq, wkv, wo, xh, wqh, wkvh, woh, &s1, &d1);
    float4 a0 = *(const float4*)(s0);
    float4 b0 = *(const float4*)(s0 + 4);
    float4 a1 = *(const float4*)(s1);
    float4 b1 = *(const float4*)(s1 + 4);
    uint4 o0, o1;
    o0.x = pkf16(a0.x, a0.y); o0.y = pkf16(a0.z, a0.w);
    o0.z = pkf16(b0.x, b0.y); o0.w = pkf16(b0.z, b0.w);
    o1.x = pkf16(a1.x, a1.y); o1.y = pkf16(a1.z, a1.w);
    o1.z = pkf16(b1.x, b1.y); o1.w = pkf16(b1.z, b1.w);
    *(uint4*)(d0) = o0;
    *(uint4*)(d1) = o1;
}

// ---------------------------------------------------------------------------
// fp16 tensor-core GEMM: C[M,N] = A[M,K] @ W[N,K]^T + bias[N], K=1024.
// CTA 128x128, 8 warps (4m x 2n), warp tile 32x64, BK=32.
// 3-stage cp.async pipeline, 2 CTAs/SM.
// ---------------------------------------------------------------------------
#define GAS 40                          // smem row stride in halfs (80 B)
#define GTILE_B (128 * GAS * 2)         // 10240 B (A or W)
#define GSTAGE_B (2 * GTILE_B)          // 20480 B per stage
#define GNC 32                          // K / 32

template<typename OT>
__device__ __forceinline__ void gemm_body(
    const __half* __restrict__ A, const __half* __restrict__ W,
    const float* __restrict__ bias, OT* __restrict__ C,
    int N, int bm, int bn, uint32_t sb)
{
    const int K = DMODEL;
    const int tid = threadIdx.x, wid = tid >> 5, lane = tid & 31;
    const int grp = lane >> 2, qid = lane & 3;
    const int rbase = (wid & 3) * 32;
    const int nbase = (wid >> 2) * 64;

    const int lrow = tid >> 1, lseg = (tid & 1) * 16;
    const __half* Ap = A + (size_t)(bm + lrow) * K + lseg;
    const __half* Wp = W + (size_t)(bn + lrow) * K + lseg;
    const uint32_t sts = (uint32_t)(lrow * GAS + lseg) * 2u;

    float acc[2][8][4];
#pragma unroll
    for (int mi = 0; mi < 2; mi++)
#pragma unroll
        for (int ni = 0; ni < 8; ni++)
#pragma unroll
            for (int v = 0; v < 4; v++) acc[mi][ni][v] = 0.0f;

    // prologue: chunks 0,1 into stages 0,1
#pragma unroll
    for (int s = 0; s < 2; s++) {
        const uint32_t st = sb + (uint32_t)s * GSTAGE_B;
        cp16(st + sts, Ap + s * 32);
        cp16(st + sts + 16, Ap + s * 32 + 8);
        cp16(st + GTILE_B + sts, Wp + s * 32);
        cp16(st + GTILE_B + sts + 16, Wp + s * 32 + 8);
        CP_COMMIT();
    }

    const uint32_t a_lo = (uint32_t)((lane & 15) * GAS + (lane >> 4) * 8) * 2u;
    const uint32_t b_lo = (uint32_t)((((lane >> 4) & 1) * 8 + (lane & 7)) * GAS
                                     + ((lane >> 3) & 1) * 8) * 2u;

    int stg_c = 0, stg_n = 2;
    for (int c = 0; c < GNC; c++) {
        CP_WAIT1();            // chunk c resident
        __syncthreads();       // everyone done with stage being refilled

        if (c + 2 < GNC) {
            const uint32_t st = sb + (uint32_t)stg_n * GSTAGE_B;
            const __half* Ap2 = Ap + (c + 2) * 32;
            const __half* Wp2 = Wp + (c + 2) * 32;
            cp16(st + sts, Ap2);
            cp16(st + sts + 16, Ap2 + 8);
            cp16(st + GTILE_B + sts, Wp2);
            cp16(st + GTILE_B + sts + 16, Wp2 + 8);
        }
        CP_COMMIT();

        const uint32_t Ab = sb + (uint32_t)stg_c * GSTAGE_B;
        const uint32_t Bb = Ab + GTILE_B;
        stg_c = (stg_c == 2) ? 0 : stg_c + 1;
        stg_n = (stg_n == 2) ? 0 : stg_n + 1;

#pragma unroll
        for (int ks = 0; ks < 2; ks++) {
            uint32_t af[2][4];
#pragma unroll
            for (int mi = 0; mi < 2; mi++)
                ldsm4(af[mi], Ab + a_lo +
                      (uint32_t)(((rbase + mi * 16) * GAS + ks * 16) * 2));
            uint32_t bf[16];
#pragma unroll
            for (int p = 0; p < 4; p++)
                ldsm4(bf + 4 * p, Bb + b_lo +
                      (uint32_t)(((nbase + p * 16) * GAS + ks * 16) * 2));
#pragma unroll
            for (int mi = 0; mi < 2; mi++)
#pragma unroll
                for (int ni = 0; ni < 8; ni++)
                    mma_f16(acc[mi][ni], af[mi], bf[2 * ni], bf[2 * ni + 1]);
        }
    }

#pragma unroll
    for (int mi = 0; mi < 2; mi++) {
        const int row = bm + rbase + mi * 16 + grp;
#pragma unroll
        for (int ni = 0; ni < 8; ni++) {
            const int col = bn + nbase + ni * 8 + 2 * qid;
            const float2 bv = *(const float2*)(bias + col);
            st_pair(C, (size_t)row * N + col,
                    acc[mi][ni][0] + bv.x, acc[mi][ni][1] + bv.y);
            st_pair(C, (size_t)(row + 8) * N + col,
                    acc[mi][ni][2] + bv.x, acc[mi][ni][3] + bv.y);
        }
    }
}

// fused Q + KV projection: grid.x covers 3072 output columns in 128-wide tiles
__global__ __launch_bounds__(256, 2) void gemm_qkv(
    const __half* __restrict__ xh,
    const __half* __restrict__ wqh, const float* __restrict__ bq,
    const __half* __restrict__ wkvh, const float* __restrict__ bkv,
    __half* __restrict__ qb, __half* __restrict__ kvb)
{
    extern __shared__ __half smh[];
    const int bnx = blockIdx.x * 128;
    if (bnx < DMODEL) {
        gemm_body<__half>(xh, wqh, bq, qb, DMODEL,
                          blockIdx.y * 128, bnx, smem_u32(smh));
    } else {
        gemm_body<__half>(xh, wkvh, bkv, kvb, 2 * DMODEL,
                          blockIdx.y * 128, bnx - DMODEL, smem_u32(smh));
    }
}

__global__ __launch_bounds__(256, 2) void gemm_hf(
    const __half* __restrict__ A, const __half* __restrict__ W,
    const float* __restrict__ bias, float* __restrict__ C, int N)
{
    extern __shared__ __half smh[];
    gemm_body<float>(A, W, bias, C, N,
                     blockIdx.y * 128, blockIdx.x * 128, smem_u32(smh));
}

// ---------------------------------------------------------------------------
// fp16 tensor-core flash attention, ALiBi + causal, exp2-domain softmax.
// l computed via ones-column in V (spare smem cols 64-71). 3-stage cp.async.
// ---------------------------------------------------------------------------
#define KSTR 72
#define KTILE_B (64 * KSTR * 2)     // 9216 B
#define ABUF_B (2 * KTILE_B)        // 18432 B per stage (K+V)

__global__ __launch_bounds__(256) void attn_mma(
    const __half* __restrict__ q, const __half* __restrict__ kv,
    __half* __restrict__ y)
{
    extern __shared__ __half smh[];
    const uint32_t sb = smem_u32(smh);

    const int tid = threadIdx.x;
    const int wid = tid >> 5, lane = tid & 31;
    const int grp = lane >> 2, qid = lane & 3;
    const int qt = (int)gridDim.x - 1 - (int)blockIdx.x;
    const int h = blockIdx.y, b = blockIdx.z;
    const int q0 = qt * 128;
    const float L2E = 1.4426950408889634f;
    const float sscale = 0.125f * L2E;
    const float slope2 = (float)(h + 1) * (1.0f / NHEAD) * L2E;

    // ---- stage Q tile into stage-0 region ----
    {
        const int row = tid >> 1;
        const int seg = (tid & 1) * 4;
        const __half* src = q + ((size_t)(b * SEQ + q0 + row)) * DMODEL
                            + h * HDIM + seg * 8;
        const uint32_t dst = sb + (uint32_t)(row * KSTR * 2 + seg * 16);
#pragma unroll
        for (int u = 0; u < 4; u++) cp16(dst + u * 16, src + u * 8);
    }
    // ---- ones-column init: V cols 64-71 = {1,0,...} for all rows, 3 stages ----
    if (tid < 192) {
        const int stg = tid >> 6, row = tid & 63;
        const uint32_t addr = sb + (uint32_t)stg * ABUF_B + (uint32_t)KTILE_B
                              + (uint32_t)(row * KSTR * 2 + 128);
        asm volatile("st.shared.v4.b32 [%0], {%1,%2,%2,%2};"
                     :: "r"(addr), "r"(0x00003C00u), "r"(0u) : "memory");
    }
    CP_COMMIT();
    CP_WAIT0();
    __syncthreads();

    const uint32_t a_lo = (uint32_t)((lane & 15) * KSTR + (lane >> 4) * 8) * 2u;
    uint32_t qfr[4][4];
    {
        const uint32_t qwarp = sb + (uint32_t)(16 * wid * KSTR * 2) + a_lo;
#pragma unroll
        for (int ks = 0; ks < 4; ks++) ldsm4(qfr[ks], qwarp + ks * 32);
    }
    __syncthreads();

    const uint32_t b_lo = (uint32_t)((((lane >> 4) & 1) * 8 + (lane & 7)) * KSTR
                                     + ((lane >> 3) & 1) * 8) * 2u;
    const uint32_t v_lo = (uint32_t)(((lane & 7) + ((lane >> 3) & 1) * 8) * KSTR
                                     + (lane >> 4) * 8) * 2u;
    const uint32_t l_lo = (uint32_t)(((lane & 15) * KSTR + 64) * 2);

    float m_[2] = {-1e30f, -1e30f};
    float oacc[8][4];
    float oaccL[4] = {0.0f, 0.0f, 0.0f, 0.0f};
#pragma unroll
    for (int ni = 0; ni < 8; ni++)
#pragma unroll
        for (int v = 0; v < 4; v++) oacc[ni][v] = 0.0f;

    const int qg0 = q0 + 16 * wid + grp;
    const int ktmax = 2 * qt + 1;

    const int krow = tid >> 2, kseg = tid & 3;
    const __half* kvbase = kv + ((size_t)(b * SEQ + krow)) * (2 * DMODEL) + h * HDIM;

    // prologue: kt 0, 1 into stages 0, 1
#pragma unroll
    for (int s = 0; s < 2; s++) {
        if (s <= ktmax) {
            const __half* src = kvbase + (size_t)(s * 64) * (2 * DMODEL);
            const uint32_t dK = sb + (uint32_t)s * ABUF_B + (uint32_t)(krow * KSTR * 2);
            const uint32_t dV = dK + (uint32_t)KTILE_B;
            cp16(dK + kseg * 16, src + kseg * 8);
            cp16(dK + (kseg + 4) * 16, src + (kseg + 4) * 8);
            cp16(dV + kseg * 16, src + DMODEL + kseg * 8);
            cp16(dV + (kseg + 4) * 16, src + DMODEL + (kseg + 4) * 8);
        }
        CP_COMMIT();
    }

    int st_c = 0, st_n = 2;
    for (int kt = 0; kt <= ktmax; kt++) {
        const int k0 = kt * 64;

        CP_WAIT1();
        __syncthreads();

        if (kt + 2 <= ktmax) {
            const __half* src = kvbase + (size_t)(k0 + 128) * (2 * DMODEL);
            const uint32_t dK = sb + (uint32_t)st_n * ABUF_B
                                + (uint32_t)(krow * KSTR * 2);
            const uint32_t dV = dK + (uint32_t)KTILE_B;
            cp16(dK + kseg * 16, src + kseg * 8);
            cp16(dK + (kseg + 4) * 16, src + (kseg + 4) * 8);
            cp16(dV + kseg * 16, src + DMODEL + kseg * 8);
            cp16(dV + (kseg + 4) * 16, src + DMODEL + (kseg + 4) * 8);
        }
        CP_COMMIT();

        const uint32_t bK = sb + (uint32_t)st_c * ABUF_B;
        const uint32_t bV = bK + (uint32_t)KTILE_B;
        st_c = (st_c == 2) ? 0 : st_c + 1;
        st_n = (st_n == 2) ? 0 : st_n + 1;

        // ---- S = Q @ K^T ----
        float sacc[8][4];
#pragma unroll
        for (int ni = 0; ni < 8; ni++)
#pragma unroll
            for (int v = 0; v < 4; v++) sacc[ni][v] = 0.0f;

#pragma unroll
        for (int ks = 0; ks < 4; ks++) {
#pragma unroll
            for (int p = 0; p < 4; p++) {
                uint32_t bf[4];
                ldsm4(bf, bK + b_lo + (uint32_t)((p * 16 * KSTR) * 2 + ks * 32));
                mma_f16(sacc[2 * p],     qfr[ks], bf[0], bf[1]);
                mma_f16(sacc[2 * p + 1], qfr[ks], bf[2], bf[3]);
            }
        }

        // ---- scale + ALiBi + causal (log2 domain, fp32) ----
        const bool needmask = (kt >= 2 * qt);
        float mx0 = -1e30f, mx1 = -1e30f;
#pragma unroll
        for (int ni = 0; ni < 8; ni++) {
            const int key0 = k0 + ni * 8 + 2 * qid;
            const float d0 = (float)(key0 - qg0);
            float v0 = fmaf(sacc[ni][0], sscale, slope2 * d0);
            float v1 = fmaf(sacc[ni][1], sscale, slope2 * (d0 + 1.0f));
            float v2 = fmaf(sacc[ni][2], sscale, slope2 * (d0 - 8.0f));
            float v3 = fmaf(sacc[ni][3], sscale, slope2 * (d0 - 7.0f));
            if (needmask) {
                if (key0     > qg0)     v0 = -1e30f;
                if (key0 + 1 > qg0)     v1 = -1e30f;
                if (key0     > qg0 + 8) v2 = -1e30f;
                if (key0 + 1 > qg0 + 8) v3 = -1e30f;
            }
            sacc[ni][0] = v0; sacc[ni][1] = v1;
            sacc[ni][2] = v2; sacc[ni][3] = v3;
            mx0 = fmaxf(mx0, fmaxf(v0, v1));
            mx1 = fmaxf(mx1, fmaxf(v2, v3));
        }
        mx0 = fmaxf(mx0, __shfl_xor_sync(0xffffffffu, mx0, 1));
        mx0 = fmaxf(mx0, __shfl_xor_sync(0xffffffffu, mx0, 2));
        mx1 = fmaxf(mx1, __shfl_xor_sync(0xffffffffu, mx1, 1));
        mx1 = fmaxf(mx1, __shfl_xor_sync(0xffffffffu, mx1, 2));

        const float mn0 = fmaxf(m_[0], mx0);
        const float mn1 = fmaxf(m_[1], mx1);
        const float sc0 = ex2f(m_[0] - mn0);
        const float sc1 = ex2f(m_[1] - mn1);
        m_[0] = mn0; m_[1] = mn1;

        // ---- P = exp2(v - mn) packed fp16x2 (sub in fp32, exp in f16x2) ----
        uint32_t P16[16];
#pragma unroll
        for (int ni = 0; ni < 8; ni++) {
            P16[2 * ni]     = ex2h2(pkf16(sacc[ni][0] - mn0, sacc[ni][1] - mn0));
            P16[2 * ni + 1] = ex2h2(pkf16(sacc[ni][2] - mn1, sacc[ni][3] - mn1));
        }

        // ---- rescale O and l ----
        oaccL[0] *= sc0; oaccL[2] *= sc1;
#pragma unroll
        for (int ni = 0; ni < 8; ni++) {
            oacc[ni][0] *= sc0; oacc[ni][1] *= sc0;
            oacc[ni][2] *= sc1; oacc[ni][3] *= sc1;
        }

        // ---- O += P @ V ; l += P @ ones (col 64) ----
#pragma unroll
        for (int kg = 0; kg < 4; kg++) {
            const uint32_t* pa = &P16[4 * kg];
#pragma unroll
            for (int dd = 0; dd < 4; dd++) {
                uint32_t vf[4];
                ldsm4t(vf, bV + v_lo +
                       (uint32_t)((kg * 16 * KSTR) * 2 + dd * 32));
                mma_f16(oacc[2 * dd],     pa, vf[0], vf[1]);
                mma_f16(oacc[2 * dd + 1], pa, vf[2], vf[3]);
            }
            uint32_t vf2[2];
            ldsm2t(vf2, bV + l_lo + (uint32_t)((kg * 16 * KSTR) * 2));
            mma_f16(oaccL, pa, vf2[0], vf2[1]);
        }
    }

    // l lives in col 64 -> qid==0 lanes; broadcast within each quad
    const float l0 = __shfl_sync(0xffffffffu, oaccL[0], lane & 28);
    const float l1 = __shfl_sync(0xffffffffu, oaccL[2], lane & 28);
    const float inv0 = 1.0f / l0;
    const float inv1 = 1.0f / l1;
    __half* d0p = y + ((size_t)(b * SEQ + qg0)) * DMODEL + h * HDIM;
    __half* d1p = d0p + (size_t)8 * DMODEL;
#pragma unroll
    for (int ni = 0; ni < 8; ni++) {
        const int c = ni * 8 + 2 * qid;
        *(uint32_t*)(d0p + c) = pkf16(oacc[ni][0] * inv0, oacc[ni][1] * inv0);
        *(uint32_t*)(d1p + c) = pkf16(oacc[ni][2] * inv1, oacc[ni][3] * inv1);
    }
}

// ---------------------------------------------------------------------------
extern "C" void kernel_launch(void* const* d_in, const int* in_sizes, int n_in,
                              void* d_out, int out_size)
{
    const float* x   = (const float*)d_in[0];
    const float* Wq  = (const float*)d_in[2];
    const float* bq  = (const float*)d_in[3];
    const float* Wkv = (const float*)d_in[4];
    const float* bkv = (const float*)d_in[5];
    const float* Wo  = (const float*)d_in[6];
    const float* bo  = (const float*)d_in[7];
    float* out = (float*)d_out;

    void *pq, *pkv, *py, *pxh, *pwq, *pwkv, *pwo;
    cudaGetSymbolAddress(&pq, g_q);
    cudaGetSymbolAddress(&pkv, g_kv);
    cudaGetSymbolAddress(&py, g_y);
    cudaGetSymbolAddress(&pxh, g_xh);
    cudaGetSymbolAddress(&pwq, g_wq);
    cudaGetSymbolAddress(&pwkv, g_wkv);
    cudaGetSymbolAddress(&pwo, g_wo);
    __half* qb   = (__half*)pq;
    __half* kvb  = (__half*)pkv;
    __half* yb   = (__half*)py;
    __half* xh   = (__half*)pxh;
    __half* wqh  = (__half*)pwq;
    __half* wkvh = (__half*)pwkv;
    __half* woh  = (__half*)pwo;

    cvt_all<<<CVT_HALF / 2048, 256>>>(x, Wq, Wkv, Wo, xh, wqh, wkvh, woh);

    const int gemm_smem = 3 * GSTAGE_B;         // 61440 B
    cudaFuncSetAttribute(gemm_qkv,
                         cudaFuncAttributeMaxDynamicSharedMemorySize, gemm_smem);
    cudaFuncSetAttribute(gemm_hf,
                         cudaFuncAttributeMaxDynamicSharedMemorySize, gemm_smem);

    // fused Q + KV projection (3072 output columns)
    gemm_qkv<<<dim3(3 * DMODEL / 128, MTOT / 128), 256, gemm_smem>>>(
        xh, wqh, bq, wkvh, bkv, qb, kvb);

    // Attention
    const int attn_smem = 3 * ABUF_B;           // 55296 B
    cudaFuncSetAttribute(attn_mma,
                         cudaFuncAttributeMaxDynamicSharedMemorySize, attn_smem);
    attn_mma<<<dim3(SEQ / 128, NHEAD, BATCH), 256, attn_smem>>>(qb, kvb, yb);

    // Output projection
    gemm_hf<<<dim3(DMODEL / 128, MTOT / 128), 256, gemm_smem>>>(
        yb, woh, bo, out, DMODEL);
}